// round 1
// baseline (speedup 1.0000x reference)
#include <cuda_runtime.h>
#include <cuda_bf16.h>
#include <math.h>

// Problem constants
#define Bsz 16
#define Hh  512
#define Ll  2048
#define Nn  64
#define Tt  64          // chunk size
#define Cc  32          // number of chunks = L/T

// ---------------- scratch (static device arrays; no allocation) ----------------
__device__ float2 g_F[Hh * Tt * Nn];   // [h][j][n] : A_n^(T-1-j)           16 MB
__device__ float2 g_E[Hh * Nn * Tt];   // [h][n][j] : Wk'_n * A_n^(j+1)     16 MB
__device__ float2 g_G[Hh * Nn];        // [h][n]    : A_n^T
__device__ float  g_ks[Hh * Tt];       // [h][m]    : k[h,m], m<T
__device__ float  g_gelu[(size_t)Bsz * Hh * Ll]; // gelu(y)                 64 MB

// ---------------- complex helpers ----------------
__device__ __forceinline__ float2 cmul(float2 a, float2 b) {
    return make_float2(a.x * b.x - a.y * b.y, a.x * b.y + a.y * b.x);
}
__device__ __forceinline__ float2 cexp2(float2 z) {
    float e = expf(z.x);
    float s, c;
    sincosf(z.y, &s, &c);
    return make_float2(e * c, e * s);
}
__device__ __forceinline__ float2 cscale(float2 z, float s) {
    return make_float2(z.x * s, z.y * s);
}

// ---------------- kernel 1: per-h mode precompute ----------------
__global__ void dss_precompute(const float* __restrict__ log_dt,
                               const float* __restrict__ Lambda,
                               const float* __restrict__ W) {
    int h = blockIdx.x;
    int n = threadIdx.x;   // 64 threads

    __shared__ float2 sWk[Nn];
    __shared__ float2 sz[Nn];

    float dt_re = expf(log_dt[h * 2 + 0]);
    float dt_im = expf(log_dt[h * 2 + 1]);
    float2 Lam = make_float2(Lambda[n * 2 + 0], Lambda[n * 2 + 1]);
    float2 z = make_float2(dt_re * Lam.x, dt_im * Lam.y);   // dt_Lambda
    bool pos = (Lam.x > 0.0f);
    float2 zn = pos ? make_float2(-z.x, -z.y) : z;

    float2 ez  = cexp2(zn);
    float2 num = make_float2(ez.x - 1.0f, ez.y);
    float2 ezL = cexp2(cscale(zn, (float)Ll));
    float2 den = make_float2(ezL.x - 1.0f, ezL.y);
    float2 x   = cmul(den, Lam);
    float r2   = x.x * x.x + x.y * x.y + 1e-7f;
    float2 recip = make_float2(x.x / r2, -x.y / r2);
    float2 Wc  = make_float2(W[(h * Nn + n) * 2 + 0], W[(h * Nn + n) * 2 + 1]);
    float2 Wk  = cmul(cmul(Wc, num), recip);
    if (pos) Wk = cmul(Wk, cexp2(cscale(z, -(float)(Ll - 1))));  // fold P_max shift

    sWk[n] = Wk;
    sz[n]  = z;
    g_G[h * Nn + n] = cexp2(cscale(z, (float)Tt));

    #pragma unroll 4
    for (int j = 0; j < Tt; j++) {
        g_F[(h * Tt + j) * Nn + n] = cexp2(cscale(z, (float)(Tt - 1 - j)));
        g_E[(h * Nn + n) * Tt + j] = cmul(Wk, cexp2(cscale(z, (float)(j + 1))));
    }
    __syncthreads();

    // kshort[m] = Re(sum_n Wk'_n * A_n^m), thread id doubles as m
    int m = n;
    float acc = 0.0f;
    for (int q = 0; q < Nn; q++) {
        float2 a  = cexp2(cscale(sz[q], (float)m));
        float2 wk = sWk[q];
        acc += wk.x * a.x - wk.y * a.y;
    }
    g_ks[h * Tt + m] = acc;
}

// ---------------- kernel 2: chunked scan conv + skip + gelu ----------------
// one block per (b,h); 256 threads; dynamic smem
__global__ __launch_bounds__(256)
void dss_conv(const float* __restrict__ u, const float* __restrict__ D) {
    extern __shared__ float smem[];
    float*  u_s  = smem;                       // 2048 floats
    float*  ks_s = smem + Ll;                  // 64 floats
    float2* buf  = (float2*)(smem + Ll + Tt);  // 4096 float2 (F, then E)
    float2* wS   = buf + Tt * Nn;              // 2048 float2 (w, then S_prev)

    int h = blockIdx.x;
    int b = blockIdx.y;
    int tid = threadIdx.x;

    const float* urow = u + ((size_t)b * Hh + h) * Ll;
    for (int i = tid; i < Ll; i += 256) u_s[i] = urow[i];
    if (tid < Tt) ks_s[tid] = g_ks[h * Tt + tid];
    const float2* Fg = g_F + (size_t)h * Tt * Nn;
    for (int i = tid; i < Tt * Nn; i += 256) buf[i] = Fg[i];
    __syncthreads();

    // Phase A: chunk partials  w[c][n] = sum_j A_n^(T-1-j) * u[c*T+j]
    {
        int n = tid & 63;
        int cs = tid >> 6;            // 0..3
        for (int cg = 0; cg < 8; cg++) {
            int c = cg * 4 + cs;
            const float* up = u_s + c * Tt;
            float2 acc = make_float2(0.0f, 0.0f);
            #pragma unroll 8
            for (int j = 0; j < Tt; j++) {
                float2 f = buf[j * Nn + n];
                float uv = up[j];
                acc.x += f.x * uv;
                acc.y += f.y * uv;
            }
            wS[c * Nn + n] = acc;
        }
    }
    __syncthreads();

    // Phase B: scan over chunks (in place: wS becomes S_prev per chunk)
    if (tid < Nn) {
        float2 G = g_G[h * Nn + tid];
        float2 S = make_float2(0.0f, 0.0f);
        for (int c = 0; c < Cc; c++) {
            float2 wv = wS[c * Nn + tid];
            wS[c * Nn + tid] = S;   // S_prev for chunk c
            float2 nsv;
            nsv.x = G.x * S.x - G.y * S.y + wv.x;
            nsv.y = G.x * S.y + G.y * S.x + wv.y;
            S = nsv;
        }
    }
    // load E (overwrites F buffer)
    {
        const float2* Eg = g_E + (size_t)h * Nn * Tt;
        for (int i = tid; i < Tt * Nn; i += 256) buf[i] = Eg[i];
    }
    __syncthreads();

    // Phase C: per-element evaluation + skip + gelu
    float Dh = D[h];
    float* gout = g_gelu + ((size_t)b * Hh + h) * Ll;
    for (int l = tid; l < Ll; l += 256) {
        int c = l >> 6;
        int j = l & 63;
        const float2* Sp = wS + c * Nn;
        float cross = 0.0f;
        #pragma unroll 8
        for (int q = 0; q < Nn; q++) {
            float2 e = buf[q * Tt + j];   // [n][j] layout: conflict-free on j
            float2 s = Sp[q];             // broadcast
            cross += e.x * s.x;
            cross -= e.y * s.y;
        }
        float within = 0.0f;
        for (int m = 0; m <= j; m++) within += ks_s[m] * u_s[l - m];
        float val = cross + within + Dh * u_s[l];
        float ge = 0.5f * val * (1.0f + erff(val * 0.70710678118654752f));
        gout[l] = ge;
    }
}

// ---------------- kernel 3: output projection GEMM + bias ----------------
// out[b,v,l] = bias[v] + sum_u Wout[v,u] * g[b,u,l]
__global__ __launch_bounds__(256)
void dss_outproj(const float* __restrict__ Wout,
                 const float* __restrict__ bias,
                 float* __restrict__ out) {
    __shared__ __align__(16) float Ws[16][64];   // [k][v]
    __shared__ __align__(16) float Gs[16][64];   // [k][l]

    int b  = blockIdx.z;
    int v0 = blockIdx.y * 64;
    int l0 = blockIdx.x * 64;
    int t  = threadIdx.x;
    int tx = t & 15;
    int ty = t >> 4;

    const float* Gb = g_gelu + (size_t)b * Hh * Ll;

    float acc[4][4];
    #pragma unroll
    for (int i = 0; i < 4; i++)
        #pragma unroll
        for (int j = 0; j < 4; j++) acc[i][j] = 0.0f;

    for (int kt = 0; kt < Hh; kt += 16) {
        {   // load 64x16 W tile (transposed into [k][v])
            int v  = t >> 2;
            int k4 = (t & 3) * 4;
            float4 wv = *(const float4*)&Wout[(size_t)(v0 + v) * Hh + kt + k4];
            Ws[k4 + 0][v] = wv.x;
            Ws[k4 + 1][v] = wv.y;
            Ws[k4 + 2][v] = wv.z;
            Ws[k4 + 3][v] = wv.w;
        }
        {   // load 16x64 G tile
            int k  = t >> 4;
            int l4 = (t & 15) * 4;
            float4 gv = *(const float4*)&Gb[(size_t)(kt + k) * Ll + l0 + l4];
            *(float4*)&Gs[k][l4] = gv;
        }
        __syncthreads();
        #pragma unroll
        for (int k = 0; k < 16; k++) {
            float4 a  = *(const float4*)&Ws[k][ty * 4];
            float4 bb = *(const float4*)&Gs[k][tx * 4];
            float av[4] = {a.x, a.y, a.z, a.w};
            float bv[4] = {bb.x, bb.y, bb.z, bb.w};
            #pragma unroll
            for (int i = 0; i < 4; i++)
                #pragma unroll
                for (int j = 0; j < 4; j++)
                    acc[i][j] += av[i] * bv[j];
        }
        __syncthreads();
    }

    #pragma unroll
    for (int i = 0; i < 4; i++) {
        int v = v0 + ty * 4 + i;
        float bs = bias[v];
        float4 o = make_float4(acc[i][0] + bs, acc[i][1] + bs,
                               acc[i][2] + bs, acc[i][3] + bs);
        *(float4*)&out[((size_t)b * Hh + v) * Ll + l0 + tx * 4] = o;
    }
}

// ---------------- launch ----------------
extern "C" void kernel_launch(void* const* d_in, const int* in_sizes, int n_in,
                              void* d_out, int out_size) {
    const float* u       = (const float*)d_in[0];  // (16,512,2048)
    const float* log_dt  = (const float*)d_in[1];  // (512,2)
    const float* Lambda  = (const float*)d_in[2];  // (64,2)
    const float* W       = (const float*)d_in[3];  // (1,512,64,2)
    const float* D       = (const float*)d_in[4];  // (1,512)
    const float* Wout    = (const float*)d_in[5];  // (512,512)
    const float* bias    = (const float*)d_in[6];  // (512,1)
    float* out = (float*)d_out;

    const int conv_smem = (Ll + Tt) * 4 + (Tt * Nn + Cc * Nn) * 8;  // 57600 B
    cudaFuncSetAttribute(dss_conv, cudaFuncAttributeMaxDynamicSharedMemorySize, conv_smem);

    dss_precompute<<<Hh, Nn>>>(log_dt, Lambda, W);
    dss_conv<<<dim3(Hh, Bsz), 256, conv_smem>>>(u, D);
    dss_outproj<<<dim3(Ll / 64, Hh / 64, Bsz), 256>>>(Wout, bias, out);
}

// round 2
// speedup vs baseline: 2.6225x; 2.6225x over previous
#include <cuda_runtime.h>
#include <cuda_bf16.h>
#include <math.h>

#define Bsz 16
#define Hh  512
#define Ll  2048
#define Nn  64
#define Tt  64
#define Cc  32
#define UP  65   // u smem pitch (floats) per chunk row
#define SP  65   // wS smem pitch (float2) per chunk row

// ---------------- scratch ----------------
__device__ float2 g_F[Hh * Tt * Nn];             // [h][j][n] : A^(63-j)
__device__ float2 g_E[Hh * Nn * Tt];             // [h][n][j] : Wk*A^(j+1)
__device__ float2 g_G[Hh * Nn];                  // [h][n]    : A^64
__device__ float  g_ks[Hh * Tt];                 // [h][m]
__device__ float  g_gelu[(size_t)Bsz * Hh * Ll]; // gelu(y)
__device__ float  g_Wt[Hh * Hh];                 // W^T [k][v]

// ---------------- complex helpers ----------------
__device__ __forceinline__ float2 cmul(float2 a, float2 b) {
    return make_float2(a.x * b.x - a.y * b.y, a.x * b.y + a.y * b.x);
}
__device__ __forceinline__ float2 cexp2(float2 z) {
    float e = expf(z.x);
    float s, c;
    sincosf(z.y, &s, &c);
    return make_float2(e * c, e * s);
}
__device__ __forceinline__ float2 cscale(float2 z, float s) {
    return make_float2(z.x * s, z.y * s);
}

// ---------------- kernel 1: per-h mode precompute (256 thr) ----------------
__global__ __launch_bounds__(256)
void dss_precompute(const float* __restrict__ log_dt,
                    const float* __restrict__ Lambda,
                    const float* __restrict__ W) {
    int h = blockIdx.x;
    int t = threadIdx.x;
    int n = t & 63;

    __shared__ float2 sWk[Nn];
    __shared__ float2 sz[Nn];
    __shared__ float  kred[Nn][4];

    if (t < 64) {
        float dt_re = expf(log_dt[h * 2 + 0]);
        float dt_im = expf(log_dt[h * 2 + 1]);
        float2 Lam = make_float2(Lambda[n * 2 + 0], Lambda[n * 2 + 1]);
        float2 z = make_float2(dt_re * Lam.x, dt_im * Lam.y);
        bool pos = (Lam.x > 0.0f);
        float2 zn = pos ? make_float2(-z.x, -z.y) : z;

        float2 ez  = cexp2(zn);
        float2 num = make_float2(ez.x - 1.0f, ez.y);
        float2 ezL = cexp2(cscale(zn, (float)Ll));
        float2 den = make_float2(ezL.x - 1.0f, ezL.y);
        float2 x   = cmul(den, Lam);
        float r2   = x.x * x.x + x.y * x.y + 1e-7f;
        float2 recip = make_float2(x.x / r2, -x.y / r2);
        float2 Wc  = make_float2(W[(h * Nn + n) * 2 + 0], W[(h * Nn + n) * 2 + 1]);
        float2 Wk  = cmul(cmul(Wc, num), recip);
        if (pos) Wk = cmul(Wk, cexp2(cscale(z, -(float)(Ll - 1))));

        sWk[n] = Wk;
        sz[n]  = z;
        g_G[h * Nn + n] = cexp2(cscale(z, (float)Tt));
    }
    __syncthreads();

    float2 z  = sz[n];
    float2 Wk = sWk[n];
    int jg = t >> 6;                 // 0..3 -> 16 j's each
    #pragma unroll 4
    for (int j = jg * 16; j < jg * 16 + 16; j++) {
        g_F[(h * Tt + j) * Nn + n] = cexp2(cscale(z, (float)(Tt - 1 - j)));
        g_E[(h * Nn + n) * Tt + j] = cmul(Wk, cexp2(cscale(z, (float)(j + 1))));
    }

    // ks[m] = Re(sum_q Wk_q * A_q^m), split q over 4 groups
    int m = t & 63;
    int qg = t >> 6;
    float acc = 0.0f;
    for (int q = qg * 16; q < qg * 16 + 16; q++) {
        float2 a = cexp2(cscale(sz[q], (float)m));
        acc += sWk[q].x * a.x - sWk[q].y * a.y;
    }
    kred[m][qg] = acc;
    __syncthreads();
    if (t < 64)
        g_ks[h * Tt + t] = kred[t][0] + kred[t][1] + kred[t][2] + kred[t][3];
}

// ---------------- kernel 1b: transpose Wout into g_Wt ----------------
__global__ void transposeW(const float* __restrict__ Wout) {
    __shared__ float tile[32][33];
    int x = blockIdx.x * 32 + threadIdx.x;
    int y = blockIdx.y * 32 + threadIdx.y;
    #pragma unroll
    for (int i = 0; i < 32; i += 8)
        tile[threadIdx.y + i][threadIdx.x] = Wout[(size_t)(y + i) * Hh + x];
    __syncthreads();
    x = blockIdx.y * 32 + threadIdx.x;
    y = blockIdx.x * 32 + threadIdx.y;
    #pragma unroll
    for (int i = 0; i < 32; i += 8)
        g_Wt[(size_t)(y + i) * Hh + x] = tile[threadIdx.x][threadIdx.y + i];
}

// ---------------- kernel 2: chunked scan conv + skip + gelu ----------------
// one block per (b,h); 256 threads
__global__ __launch_bounds__(256)
void dss_conv(const float* __restrict__ u, const float* __restrict__ D) {
    extern __shared__ float smem[];
    float*  u_s  = smem;                        // 32*65 floats (padded)
    float*  ks_s = smem + Cc * UP;              // 64 floats
    float2* buf  = (float2*)(smem + Cc * UP + Tt);   // 4096 float2 (F then E)
    float2* wS   = buf + Tt * Nn;               // 32*65 float2 (padded)

    int b = blockIdx.x;
    int h = blockIdx.y;
    int t = threadIdx.x;

    const float* urow = u + ((size_t)b * Hh + h) * Ll;
    for (int i = t; i < Ll; i += 256)
        u_s[(i >> 6) * UP + (i & 63)] = urow[i];
    if (t < Tt) ks_s[t] = g_ks[h * Tt + t];
    const float2* Fg = g_F + (size_t)h * Tt * Nn;
    for (int i = t; i < Tt * Nn; i += 256) buf[i] = Fg[i];
    __syncthreads();

    // Phase A: w[c][n] = sum_j A_n^(63-j) u[c*64+j]
    // thread: n0 = (t>>4)*4 (4 n's), cc = t&15 (c in {cc, cc+16})
    {
        int n0 = (t >> 4) * 4;
        int cc = t & 15;
        float ar0[4] = {0,0,0,0}, ai0[4] = {0,0,0,0};
        float ar1[4] = {0,0,0,0}, ai1[4] = {0,0,0,0};
        const float* u0 = u_s + cc * UP;
        const float* u1 = u_s + (cc + 16) * UP;
        #pragma unroll 4
        for (int j = 0; j < Tt; j++) {
            float4 f01 = *(const float4*)&buf[j * Nn + n0];
            float4 f23 = *(const float4*)&buf[j * Nn + n0 + 2];
            float uv0 = u0[j], uv1 = u1[j];
            ar0[0] += f01.x * uv0; ai0[0] += f01.y * uv0;
            ar0[1] += f01.z * uv0; ai0[1] += f01.w * uv0;
            ar0[2] += f23.x * uv0; ai0[2] += f23.y * uv0;
            ar0[3] += f23.z * uv0; ai0[3] += f23.w * uv0;
            ar1[0] += f01.x * uv1; ai1[0] += f01.y * uv1;
            ar1[1] += f01.z * uv1; ai1[1] += f01.w * uv1;
            ar1[2] += f23.x * uv1; ai1[2] += f23.y * uv1;
            ar1[3] += f23.z * uv1; ai1[3] += f23.w * uv1;
        }
        #pragma unroll
        for (int i = 0; i < 4; i++) {
            wS[cc * SP + n0 + i]        = make_float2(ar0[i], ai0[i]);
            wS[(cc + 16) * SP + n0 + i] = make_float2(ar1[i], ai1[i]);
        }
    }
    __syncthreads();

    // Phase B: cross-chunk scan (threads 0..63), in place -> S_prev per chunk
    if (t < Nn) {
        float2 G = g_G[h * Nn + t];
        float2 S = make_float2(0.0f, 0.0f);
        for (int c = 0; c < Cc; c++) {
            float2 wv = wS[c * SP + t];
            wS[c * SP + t] = S;
            float2 nsv;
            nsv.x = G.x * S.x - G.y * S.y + wv.x;
            nsv.y = G.x * S.y + G.y * S.x + wv.y;
            S = nsv;
        }
    }
    // load E (overwrites F buffer); all threads participate
    {
        const float2* Eg = g_E + (size_t)h * Nn * Tt;
        for (int i = t; i < Tt * Nn; i += 256) buf[i] = Eg[i];
    }
    __syncthreads();

    // Phase C: cross term + within-chunk conv + skip + gelu
    // thread: jg = t>>4 -> j0 = jg*4 (4 j's), cc = t&15 (c in {cc, cc+16})
    {
        int jg = t >> 4;
        int j0 = jg * 4;
        int cc = t & 15;
        float acc[2][4] = {{0,0,0,0},{0,0,0,0}};

        const float2* Sp0 = wS + cc * SP;
        const float2* Sp1 = wS + (cc + 16) * SP;
        #pragma unroll 4
        for (int q = 0; q < Nn; q++) {
            float4 e01 = *(const float4*)&buf[q * Tt + j0];
            float4 e23 = *(const float4*)&buf[q * Tt + j0 + 2];
            float2 s0 = Sp0[q];
            float2 s1 = Sp1[q];
            acc[0][0] += e01.x * s0.x - e01.y * s0.y;
            acc[0][1] += e01.z * s0.x - e01.w * s0.y;
            acc[0][2] += e23.x * s0.x - e23.y * s0.y;
            acc[0][3] += e23.z * s0.x - e23.w * s0.y;
            acc[1][0] += e01.x * s1.x - e01.y * s1.y;
            acc[1][1] += e01.z * s1.x - e01.w * s1.y;
            acc[1][2] += e23.x * s1.x - e23.y * s1.y;
            acc[1][3] += e23.z * s1.x - e23.w * s1.y;
        }

        float Dh = D[h];
        #pragma unroll
        for (int ci = 0; ci < 2; ci++) {
            int c = cc + ci * 16;
            const float* ub = u_s + c * UP;
            // sliding window: win[i] = u[c*64 + j0 + i - m]
            float win[4];
            #pragma unroll
            for (int i = 0; i < 4; i++) win[i] = ub[j0 + i];
            for (int m = 0; m <= j0; m++) {
                float km = ks_s[m];
                acc[ci][0] += km * win[0];
                acc[ci][1] += km * win[1];
                acc[ci][2] += km * win[2];
                acc[ci][3] += km * win[3];
                win[3] = win[2]; win[2] = win[1]; win[1] = win[0];
                int idx = j0 - m - 1;
                win[0] = (idx >= 0) ? ub[idx] : 0.0f;
            }
            #pragma unroll
            for (int mt = 1; mt <= 3; mt++) {
                float km = ks_s[j0 + mt];
                #pragma unroll
                for (int i = 0; i < 4; i++)
                    if (i >= mt) acc[ci][i] += km * win[i];
                win[3] = win[2]; win[2] = win[1]; win[1] = win[0];
                win[0] = 0.0f;
            }
            // skip + gelu + store
            float4 o;
            float v0 = acc[ci][0] + Dh * ub[j0 + 0];
            float v1 = acc[ci][1] + Dh * ub[j0 + 1];
            float v2 = acc[ci][2] + Dh * ub[j0 + 2];
            float v3 = acc[ci][3] + Dh * ub[j0 + 3];
            o.x = 0.5f * v0 * (1.0f + erff(v0 * 0.70710678118654752f));
            o.y = 0.5f * v1 * (1.0f + erff(v1 * 0.70710678118654752f));
            o.z = 0.5f * v2 * (1.0f + erff(v2 * 0.70710678118654752f));
            o.w = 0.5f * v3 * (1.0f + erff(v3 * 0.70710678118654752f));
            float* gout = g_gelu + ((size_t)b * Hh + h) * Ll;
            *(float4*)&gout[c * Tt + j0] = o;
        }
    }
}

// ---------------- kernel 3: output projection 128x128x16, 8x8 micro ----------------
__global__ __launch_bounds__(256)
void dss_outproj(const float* __restrict__ bias, float* __restrict__ out) {
    __shared__ __align__(16) float Ws[16][128];   // [k][v]
    __shared__ __align__(16) float Gs[16][128];   // [k][l]

    int b  = blockIdx.z;
    int v0 = blockIdx.y * 128;
    int l0 = blockIdx.x * 128;
    int t  = threadIdx.x;
    int tx = t & 15;
    int ty = t >> 4;

    const float* Gb = g_gelu + (size_t)b * Hh * Ll + l0;

    float acc[8][8];
    #pragma unroll
    for (int i = 0; i < 8; i++)
        #pragma unroll
        for (int j = 0; j < 8; j++) acc[i][j] = 0.0f;

    int lk = t >> 5;          // 0..7
    int lc = (t & 31) * 4;    // column float4 start

    for (int kt = 0; kt < Hh; kt += 16) {
        *(float4*)&Ws[lk][lc]     = *(const float4*)&g_Wt[(size_t)(kt + lk) * Hh + v0 + lc];
        *(float4*)&Ws[lk + 8][lc] = *(const float4*)&g_Wt[(size_t)(kt + lk + 8) * Hh + v0 + lc];
        *(float4*)&Gs[lk][lc]     = *(const float4*)&Gb[(size_t)(kt + lk) * Ll + lc];
        *(float4*)&Gs[lk + 8][lc] = *(const float4*)&Gb[(size_t)(kt + lk + 8) * Ll + lc];
        __syncthreads();
        #pragma unroll
        for (int k = 0; k < 16; k++) {
            float a[8], g[8];
            *(float4*)&a[0] = *(const float4*)&Ws[k][ty * 4];
            *(float4*)&a[4] = *(const float4*)&Ws[k][64 + ty * 4];
            *(float4*)&g[0] = *(const float4*)&Gs[k][tx * 4];
            *(float4*)&g[4] = *(const float4*)&Gs[k][64 + tx * 4];
            #pragma unroll
            for (int i = 0; i < 8; i++)
                #pragma unroll
                for (int j = 0; j < 8; j++)
                    acc[i][j] += a[i] * g[j];
        }
        __syncthreads();
    }

    #pragma unroll
    for (int i = 0; i < 8; i++) {
        int v = v0 + ((i < 4) ? (ty * 4 + i) : (64 + ty * 4 + i - 4));
        float bs = bias[v];
        float4 o0 = make_float4(acc[i][0] + bs, acc[i][1] + bs,
                                acc[i][2] + bs, acc[i][3] + bs);
        float4 o1 = make_float4(acc[i][4] + bs, acc[i][5] + bs,
                                acc[i][6] + bs, acc[i][7] + bs);
        float* orow = out + ((size_t)b * Hh + v) * Ll + l0;
        *(float4*)&orow[tx * 4]      = o0;
        *(float4*)&orow[64 + tx * 4] = o1;
    }
}

// ---------------- launch ----------------
extern "C" void kernel_launch(void* const* d_in, const int* in_sizes, int n_in,
                              void* d_out, int out_size) {
    const float* u       = (const float*)d_in[0];
    const float* log_dt  = (const float*)d_in[1];
    const float* Lambda  = (const float*)d_in[2];
    const float* W       = (const float*)d_in[3];
    const float* D       = (const float*)d_in[4];
    const float* Wout    = (const float*)d_in[5];
    const float* bias    = (const float*)d_in[6];
    float* out = (float*)d_out;

    const int conv_smem = (Cc * UP + Tt) * 4 + (Tt * Nn + Cc * SP) * 8;  // 57984 B
    static bool attr_set = false;
    if (!attr_set) {
        cudaFuncSetAttribute(dss_conv, cudaFuncAttributeMaxDynamicSharedMemorySize, conv_smem);
        attr_set = true;
    }

    dss_precompute<<<Hh, 256>>>(log_dt, Lambda, W);
    transposeW<<<dim3(16, 16), dim3(32, 8)>>>(Wout);
    dss_conv<<<dim3(Bsz, Hh), 256, conv_smem>>>(u, D);
    dss_outproj<<<dim3(Ll / 128, Hh / 128, Bsz), 256>>>(bias, out);
}

// round 5
// speedup vs baseline: 3.3982x; 1.2958x over previous
#include <cuda_runtime.h>
#include <cuda_bf16.h>
#include <cstdint>
#include <cstddef>
#include <math.h>

#define Bsz 16
#define Hh  512
#define Ll  2048
#define Nn  64
#define Tt  64
#define Cc  32
#define UP  65   // u smem pitch (floats)
#define SP  65   // wS smem pitch (float2)

// ---------------- scratch ----------------
__device__ float2 g_F[Hh * Tt * Nn];             // [h][j][n] : A^(63-j)
__device__ float2 g_E[Hh * Nn * Tt];             // [h][n][j] : Wk*A^(j+1)
__device__ float2 g_G[Hh * Nn];                  // [h][n]    : A^64
__device__ float  g_ks[Hh * Tt];                 // [h][m]
__device__ __nv_bfloat16 g_ghi[(size_t)Bsz * Hh * Ll];  // gelu hi
__device__ __nv_bfloat16 g_glo[(size_t)Bsz * Hh * Ll];  // gelu lo
__device__ __nv_bfloat16 g_Whi[Hh * Hh];         // Wout hi [v][u]
__device__ __nv_bfloat16 g_Wlo[Hh * Hh];         // Wout lo [v][u]

// ---------------- helpers ----------------
__device__ __forceinline__ float2 cmul(float2 a, float2 b) {
    return make_float2(a.x * b.x - a.y * b.y, a.x * b.y + a.y * b.x);
}
__device__ __forceinline__ float2 cexp2(float2 z) {
    float e = expf(z.x);
    float s, c;
    sincosf(z.y, &s, &c);
    return make_float2(e * c, e * s);
}
__device__ __forceinline__ float2 cscale(float2 z, float s) {
    return make_float2(z.x * s, z.y * s);
}
__device__ __forceinline__ uint32_t packbf(float a, float b) {
    __nv_bfloat162 t = __floats2bfloat162_rn(a, b);
    return *reinterpret_cast<uint32_t*>(&t);
}
__device__ __forceinline__ uint32_t smem_u32(const void* p) {
    return (uint32_t)__cvta_generic_to_shared(p);
}
__device__ __forceinline__ void ldsm_x4(uint32_t& r0, uint32_t& r1, uint32_t& r2, uint32_t& r3, uint32_t a) {
    asm volatile("ldmatrix.sync.aligned.m8n8.x4.shared.b16 {%0,%1,%2,%3},[%4];"
                 : "=r"(r0), "=r"(r1), "=r"(r2), "=r"(r3) : "r"(a));
}
__device__ __forceinline__ void ldsm_x4_t(uint32_t& r0, uint32_t& r1, uint32_t& r2, uint32_t& r3, uint32_t a) {
    asm volatile("ldmatrix.sync.aligned.m8n8.x4.trans.shared.b16 {%0,%1,%2,%3},[%4];"
                 : "=r"(r0), "=r"(r1), "=r"(r2), "=r"(r3) : "r"(a));
}
__device__ __forceinline__ void mma_bf16(float* d, const uint32_t* a, const uint32_t* b) {
    asm volatile("mma.sync.aligned.m16n8k16.row.col.f32.bf16.bf16.f32 "
                 "{%0,%1,%2,%3},{%4,%5,%6,%7},{%8,%9},{%0,%1,%2,%3};"
                 : "+f"(d[0]), "+f"(d[1]), "+f"(d[2]), "+f"(d[3])
                 : "r"(a[0]), "r"(a[1]), "r"(a[2]), "r"(a[3]), "r"(b[0]), "r"(b[1]));
}

// ---------------- kernel 1: precompute via power recurrence ----------------
__global__ __launch_bounds__(64)
void dss_precompute(const float* __restrict__ log_dt,
                    const float* __restrict__ Lambda,
                    const float* __restrict__ W) {
    int h = blockIdx.x;
    int n = threadIdx.x;

    __shared__ float2 sE[Nn][Tt + 1];
    __shared__ float2 sWk[Nn];

    float dt_re = expf(log_dt[h * 2 + 0]);
    float dt_im = expf(log_dt[h * 2 + 1]);
    float2 Lam = make_float2(Lambda[n * 2 + 0], Lambda[n * 2 + 1]);
    float2 z = make_float2(dt_re * Lam.x, dt_im * Lam.y);
    bool pos = (Lam.x > 0.0f);
    float2 zn = pos ? make_float2(-z.x, -z.y) : z;

    float2 ez  = cexp2(zn);
    float2 num = make_float2(ez.x - 1.0f, ez.y);
    float2 ezL = cexp2(cscale(zn, (float)Ll));
    float2 den = make_float2(ezL.x - 1.0f, ezL.y);
    float2 x   = cmul(den, Lam);
    float r2   = x.x * x.x + x.y * x.y + 1e-7f;
    float2 recip = make_float2(x.x / r2, -x.y / r2);
    float2 Wc  = make_float2(W[(h * Nn + n) * 2 + 0], W[(h * Nn + n) * 2 + 1]);
    float2 Wk  = cmul(cmul(Wc, num), recip);
    if (pos) Wk = cmul(Wk, cexp2(cscale(z, -(float)(Ll - 1))));

    sWk[n] = Wk;

    float2 A  = cexp2(z);
    float2 Ap = make_float2(1.0f, 0.0f);   // A^p
    for (int p = 0; p <= 64; p++) {
        if (p <= 63) g_F[(h * Tt + (63 - p)) * Nn + n] = Ap;
        if (p == 64) g_G[h * Nn + n] = Ap;
        if (p >= 1)  sE[n][p - 1] = cmul(Wk, Ap);
        Ap = cmul(Ap, A);
    }
    __syncthreads();

    // ks[m]: m=0 -> sum Re(Wk); m>=1 -> sum_n sE[n][m-1].x
    int m = n;
    float acc = 0.0f;
    if (m == 0) {
        for (int q = 0; q < Nn; q++) acc += sWk[q].x;
    } else {
        for (int q = 0; q < Nn; q++) acc += sE[q][m - 1].x;
    }
    g_ks[h * Tt + m] = acc;

    // coalesced E writeback
    for (int i = n; i < Nn * Tt; i += 64)
        g_E[h * Nn * Tt + i] = sE[i >> 6][i & 63];
}

// ---------------- kernel 1b: split Wout into bf16 hi/lo ----------------
__global__ void splitW(const float* __restrict__ Wout) {
    int i = blockIdx.x * 256 + threadIdx.x;
    float w = Wout[i];
    __nv_bfloat16 hi = __float2bfloat16(w);
    g_Whi[i] = hi;
    g_Wlo[i] = __float2bfloat16(w - __bfloat162float(hi));
}

// ---------------- kernel 2: chunked scan conv + skip + gelu ----------------
__global__ __launch_bounds__(256)
void dss_conv(const float* __restrict__ u, const float* __restrict__ D) {
    extern __shared__ float smem[];
    float*  u_s  = smem;
    float*  ks_s = smem + Cc * UP;
    float2* buf  = (float2*)(smem + Cc * UP + Tt);
    float2* wS   = buf + Tt * Nn;

    int b = blockIdx.x;
    int h = blockIdx.y;
    int t = threadIdx.x;

    const float* urow = u + ((size_t)b * Hh + h) * Ll;
    for (int i = t; i < Ll; i += 256)
        u_s[(i >> 6) * UP + (i & 63)] = urow[i];
    if (t < Tt) ks_s[t] = g_ks[h * Tt + t];
    const float2* Fg = g_F + (size_t)h * Tt * Nn;
    for (int i = t; i < Tt * Nn; i += 256) buf[i] = Fg[i];
    __syncthreads();

    // Phase A
    {
        int n0 = (t >> 4) * 4;
        int cc = t & 15;
        float ar0[4] = {0,0,0,0}, ai0[4] = {0,0,0,0};
        float ar1[4] = {0,0,0,0}, ai1[4] = {0,0,0,0};
        const float* u0 = u_s + cc * UP;
        const float* u1 = u_s + (cc + 16) * UP;
        #pragma unroll 4
        for (int j = 0; j < Tt; j++) {
            float4 f01 = *(const float4*)&buf[j * Nn + n0];
            float4 f23 = *(const float4*)&buf[j * Nn + n0 + 2];
            float uv0 = u0[j], uv1 = u1[j];
            ar0[0] += f01.x * uv0; ai0[0] += f01.y * uv0;
            ar0[1] += f01.z * uv0; ai0[1] += f01.w * uv0;
            ar0[2] += f23.x * uv0; ai0[2] += f23.y * uv0;
            ar0[3] += f23.z * uv0; ai0[3] += f23.w * uv0;
            ar1[0] += f01.x * uv1; ai1[0] += f01.y * uv1;
            ar1[1] += f01.z * uv1; ai1[1] += f01.w * uv1;
            ar1[2] += f23.x * uv1; ai1[2] += f23.y * uv1;
            ar1[3] += f23.z * uv1; ai1[3] += f23.w * uv1;
        }
        #pragma unroll
        for (int i = 0; i < 4; i++) {
            wS[cc * SP + n0 + i]        = make_float2(ar0[i], ai0[i]);
            wS[(cc + 16) * SP + n0 + i] = make_float2(ar1[i], ai1[i]);
        }
    }
    __syncthreads();

    // Phase B: cross-chunk scan
    if (t < Nn) {
        float2 G = g_G[h * Nn + t];
        float2 S = make_float2(0.0f, 0.0f);
        for (int c = 0; c < Cc; c++) {
            float2 wv = wS[c * SP + t];
            wS[c * SP + t] = S;
            float2 nsv;
            nsv.x = G.x * S.x - G.y * S.y + wv.x;
            nsv.y = G.x * S.y + G.y * S.x + wv.y;
            S = nsv;
        }
    }
    {
        const float2* Eg = g_E + (size_t)h * Nn * Tt;
        for (int i = t; i < Tt * Nn; i += 256) buf[i] = Eg[i];
    }
    __syncthreads();

    // Phase C
    {
        int jg = t >> 4;
        int j0 = jg * 4;
        int cc = t & 15;
        float acc[2][4] = {{0,0,0,0},{0,0,0,0}};

        const float2* Sp0 = wS + cc * SP;
        const float2* Sp1 = wS + (cc + 16) * SP;
        #pragma unroll 4
        for (int q = 0; q < Nn; q++) {
            float4 e01 = *(const float4*)&buf[q * Tt + j0];
            float4 e23 = *(const float4*)&buf[q * Tt + j0 + 2];
            float2 s0 = Sp0[q];
            float2 s1 = Sp1[q];
            acc[0][0] += e01.x * s0.x - e01.y * s0.y;
            acc[0][1] += e01.z * s0.x - e01.w * s0.y;
            acc[0][2] += e23.x * s0.x - e23.y * s0.y;
            acc[0][3] += e23.z * s0.x - e23.w * s0.y;
            acc[1][0] += e01.x * s1.x - e01.y * s1.y;
            acc[1][1] += e01.z * s1.x - e01.w * s1.y;
            acc[1][2] += e23.x * s1.x - e23.y * s1.y;
            acc[1][3] += e23.z * s1.x - e23.w * s1.y;
        }

        float Dh = D[h];
        #pragma unroll
        for (int ci = 0; ci < 2; ci++) {
            int c = cc + ci * 16;
            const float* ub = u_s + c * UP;
            float win[4];
            #pragma unroll
            for (int i = 0; i < 4; i++) win[i] = ub[j0 + i];
            for (int m = 0; m <= j0; m++) {
                float km = ks_s[m];
                acc[ci][0] += km * win[0];
                acc[ci][1] += km * win[1];
                acc[ci][2] += km * win[2];
                acc[ci][3] += km * win[3];
                win[3] = win[2]; win[2] = win[1]; win[1] = win[0];
                int idx = j0 - m - 1;
                win[0] = (idx >= 0) ? ub[idx] : 0.0f;
            }
            #pragma unroll
            for (int mt = 1; mt <= 3; mt++) {
                float km = ks_s[j0 + mt];
                #pragma unroll
                for (int i = 0; i < 4; i++)
                    if (i >= mt) acc[ci][i] += km * win[i];
                win[3] = win[2]; win[2] = win[1]; win[1] = win[0];
                win[0] = 0.0f;
            }
            float g0 = acc[ci][0] + Dh * ub[j0 + 0];
            float g1 = acc[ci][1] + Dh * ub[j0 + 1];
            float g2 = acc[ci][2] + Dh * ub[j0 + 2];
            float g3 = acc[ci][3] + Dh * ub[j0 + 3];
            g0 = 0.5f * g0 * (1.0f + erff(g0 * 0.70710678118654752f));
            g1 = 0.5f * g1 * (1.0f + erff(g1 * 0.70710678118654752f));
            g2 = 0.5f * g2 * (1.0f + erff(g2 * 0.70710678118654752f));
            g3 = 0.5f * g3 * (1.0f + erff(g3 * 0.70710678118654752f));

            float h0f = __bfloat162float(__float2bfloat16(g0));
            float h1f = __bfloat162float(__float2bfloat16(g1));
            float h2f = __bfloat162float(__float2bfloat16(g2));
            float h3f = __bfloat162float(__float2bfloat16(g3));

            size_t base = ((size_t)b * Hh + h) * Ll + c * Tt + j0;
            *reinterpret_cast<uint32_t*>(&g_ghi[base])     = packbf(g0, g1);
            *reinterpret_cast<uint32_t*>(&g_ghi[base + 2]) = packbf(g2, g3);
            *reinterpret_cast<uint32_t*>(&g_glo[base])     = packbf(g0 - h0f, g1 - h1f);
            *reinterpret_cast<uint32_t*>(&g_glo[base + 2]) = packbf(g2 - h2f, g3 - h3f);
        }
    }
}

// ---------------- kernel 3: outproj via mma.sync bf16 3-way split ----------------
// out[b][v][l] = bias[v] + sum_u Wout[v][u] * g[b][u][l]
// block tile 128(v) x 128(l), k-step 32; 8 warps: 2(v) x 4(l), warp tile 64x32
__global__ __launch_bounds__(256)
void dss_outproj(const float* __restrict__ bias, float* __restrict__ out) {
    __shared__ __align__(16) __nv_bfloat16 As[2][128][40];   // [hi/lo][v][k]
    __shared__ __align__(16) __nv_bfloat16 Bs[2][32][136];   // [hi/lo][k][l]

    int b  = blockIdx.z;
    int v0 = blockIdx.y * 128;
    int l0 = blockIdx.x * 128;
    int t  = threadIdx.x;
    int lane = t & 31;
    int wrp  = t >> 5;
    int wv = wrp >> 2;       // 0..1
    int wl = wrp & 3;        // 0..3

    float acc[4][4][4];
    #pragma unroll
    for (int i = 0; i < 4; i++)
        #pragma unroll
        for (int j = 0; j < 4; j++)
            #pragma unroll
            for (int r = 0; r < 4; r++) acc[i][j][r] = 0.0f;

    const int arow = t >> 2;
    const int aseg = (t & 3) * 8;
    const int brow = t >> 4;
    const int bseg = (t & 15) * 8;

    for (int kt = 0; kt < Hh; kt += 32) {
        #pragma unroll
        for (int rep = 0; rep < 2; rep++) {
            int r128 = rep * 64 + arow;
            *(uint4*)&As[0][r128][aseg] =
                *(const uint4*)&g_Whi[(size_t)(v0 + r128) * Hh + kt + aseg];
            *(uint4*)&As[1][r128][aseg] =
                *(const uint4*)&g_Wlo[(size_t)(v0 + r128) * Hh + kt + aseg];
            int r32 = rep * 16 + brow;
            *(uint4*)&Bs[0][r32][bseg] =
                *(const uint4*)&g_ghi[((size_t)b * Hh + kt + r32) * Ll + l0 + bseg];
            *(uint4*)&Bs[1][r32][bseg] =
                *(const uint4*)&g_glo[((size_t)b * Hh + kt + r32) * Ll + l0 + bseg];
        }
        __syncthreads();

        #pragma unroll
        for (int kk = 0; kk < 2; kk++) {
            uint32_t a_hi[4][4], a_lo[4][4], b_hi[4][2], b_lo[4][2];
            int ar = (lane & 15);
            int ac = kk * 16 + ((lane >> 4) << 3);
            #pragma unroll
            for (int mi = 0; mi < 4; mi++) {
                int row = wv * 64 + mi * 16 + ar;
                ldsm_x4(a_hi[mi][0], a_hi[mi][1], a_hi[mi][2], a_hi[mi][3],
                        smem_u32(&As[0][row][ac]));
                ldsm_x4(a_lo[mi][0], a_lo[mi][1], a_lo[mi][2], a_lo[mi][3],
                        smem_u32(&As[1][row][ac]));
            }
            int brw = kk * 16 + (lane & 15);
            #pragma unroll
            for (int nj = 0; nj < 2; nj++) {
                int bc = wl * 32 + nj * 16 + ((lane >> 4) << 3);
                uint32_t r0, r1, r2, r3;
                ldsm_x4_t(r0, r1, r2, r3, smem_u32(&Bs[0][brw][bc]));
                b_hi[2 * nj][0] = r0; b_hi[2 * nj][1] = r1;
                b_hi[2 * nj + 1][0] = r2; b_hi[2 * nj + 1][1] = r3;
                ldsm_x4_t(r0, r1, r2, r3, smem_u32(&Bs[1][brw][bc]));
                b_lo[2 * nj][0] = r0; b_lo[2 * nj][1] = r1;
                b_lo[2 * nj + 1][0] = r2; b_lo[2 * nj + 1][1] = r3;
            }
            #pragma unroll
            for (int mi = 0; mi < 4; mi++)
                #pragma unroll
                for (int ni = 0; ni < 4; ni++) {
                    mma_bf16(acc[mi][ni], a_hi[mi], b_hi[ni]);
                    mma_bf16(acc[mi][ni], a_hi[mi], b_lo[ni]);
                    mma_bf16(acc[mi][ni], a_lo[mi], b_hi[ni]);
                }
        }
        __syncthreads();
    }

    // epilogue
    int row = lane >> 2;
    int col = (lane & 3) * 2;
    #pragma unroll
    for (int mi = 0; mi < 4; mi++) {
        int v = v0 + wv * 64 + mi * 16 + row;
        float bs0 = bias[v];
        float bs1 = bias[v + 8];
        float* o0 = out + ((size_t)b * Hh + v) * Ll;
        float* o1 = out + ((size_t)b * Hh + v + 8) * Ll;
        #pragma unroll
        for (int ni = 0; ni < 4; ni++) {
            int l = l0 + wl * 32 + ni * 8 + col;
            float2 p0 = make_float2(acc[mi][ni][0] + bs0, acc[mi][ni][1] + bs0);
            float2 p1 = make_float2(acc[mi][ni][2] + bs1, acc[mi][ni][3] + bs1);
            *(float2*)&o0[l] = p0;
            *(float2*)&o1[l] = p1;
        }
    }
}

// ---------------- launch ----------------
extern "C" void kernel_launch(void* const* d_in, const int* in_sizes, int n_in,
                              void* d_out, int out_size) {
    const float* u       = (const float*)d_in[0];
    const float* log_dt  = (const float*)d_in[1];
    const float* Lambda  = (const float*)d_in[2];
    const float* W       = (const float*)d_in[3];
    const float* D       = (const float*)d_in[4];
    const float* Wout    = (const float*)d_in[5];
    const float* bias    = (const float*)d_in[6];
    float* out = (float*)d_out;

    const int conv_smem = (Cc * UP + Tt) * 4 + (Tt * Nn + Cc * SP) * 8;
    static bool attr_set = false;
    if (!attr_set) {
        cudaFuncSetAttribute(dss_conv, cudaFuncAttributeMaxDynamicSharedMemorySize, conv_smem);
        attr_set = true;
    }

    dss_precompute<<<Hh, Nn>>>(log_dt, Lambda, W);
    splitW<<<Hh * Hh / 256, 256>>>(Wout);
    dss_conv<<<dim3(Bsz, Hh), 256, conv_smem>>>(u, D);
    dss_outproj<<<dim3(Ll / 128, Hh / 128, Bsz), 256>>>(bias, out);
}

// round 6
// speedup vs baseline: 6.5625x; 1.9312x over previous
#include <cuda_runtime.h>
#include <cuda_bf16.h>
#include <cstdint>
#include <cstddef>
#include <math.h>

#define Bsz 16
#define Hh  512
#define Ll  2048
#define Nn  64
#define Tt  64
#define Cc  32

// ---------------- scratch ----------------
__device__ float2   g_G[Hh * Nn];                 // [h][n] : A^64
__device__ uint32_t g_B1hi[(size_t)Hh * 6144];    // GEMM1 B frags (hi): [h][ks4][nt24][lane][2]
__device__ uint32_t g_B1lo[(size_t)Hh * 6144];
__device__ uint32_t g_B2hi[(size_t)Hh * 4096];    // GEMM2 B frags (hi): [h][ks8][nt8][lane][2]
__device__ uint32_t g_B2lo[(size_t)Hh * 4096];
__device__ __nv_bfloat16 g_ghi[(size_t)Bsz * Hh * Ll];  // gelu hi
__device__ __nv_bfloat16 g_glo[(size_t)Bsz * Hh * Ll];  // gelu lo
__device__ __nv_bfloat16 g_Whi[Hh * Hh];          // Wout hi [v][u]
__device__ __nv_bfloat16 g_Wlo[Hh * Hh];          // Wout lo [v][u]

// ---------------- helpers ----------------
__device__ __forceinline__ float2 cmul(float2 a, float2 b) {
    return make_float2(a.x * b.x - a.y * b.y, a.x * b.y + a.y * b.x);
}
__device__ __forceinline__ float2 cexp2(float2 z) {
    float e = expf(z.x);
    float s, c;
    sincosf(z.y, &s, &c);
    return make_float2(e * c, e * s);
}
__device__ __forceinline__ float2 cscale(float2 z, float s) {
    return make_float2(z.x * s, z.y * s);
}
__device__ __forceinline__ uint32_t packbf(float a, float b) {
    __nv_bfloat162 t = __floats2bfloat162_rn(a, b);
    return *reinterpret_cast<uint32_t*>(&t);
}
__device__ __forceinline__ float2 unpack2(uint32_t x) {
    __nv_bfloat162 t = *reinterpret_cast<__nv_bfloat162*>(&x);
    return make_float2(__bfloat162float(t.x), __bfloat162float(t.y));
}
// split pair (v0,v1) into bf16 hi and lo words
__device__ __forceinline__ void split2(float v0, float v1, uint32_t& hi, uint32_t& lo) {
    __nv_bfloat162 h2 = __floats2bfloat162_rn(v0, v1);
    hi = *reinterpret_cast<uint32_t*>(&h2);
    float r0 = v0 - __bfloat162float(h2.x);
    float r1 = v1 - __bfloat162float(h2.y);
    __nv_bfloat162 l2 = __floats2bfloat162_rn(r0, r1);
    lo = *reinterpret_cast<uint32_t*>(&l2);
}
__device__ __forceinline__ uint32_t smem_u32(const void* p) {
    return (uint32_t)__cvta_generic_to_shared(p);
}
__device__ __forceinline__ void ldsm_x4(uint32_t& r0, uint32_t& r1, uint32_t& r2, uint32_t& r3, uint32_t a) {
    asm volatile("ldmatrix.sync.aligned.m8n8.x4.shared.b16 {%0,%1,%2,%3},[%4];"
                 : "=r"(r0), "=r"(r1), "=r"(r2), "=r"(r3) : "r"(a));
}
__device__ __forceinline__ void ldsm_x4_t(uint32_t& r0, uint32_t& r1, uint32_t& r2, uint32_t& r3, uint32_t a) {
    asm volatile("ldmatrix.sync.aligned.m8n8.x4.trans.shared.b16 {%0,%1,%2,%3},[%4];"
                 : "=r"(r0), "=r"(r1), "=r"(r2), "=r"(r3) : "r"(a));
}
__device__ __forceinline__ void mma_bf16(float* d, const uint32_t* a, const uint32_t* b) {
    asm volatile("mma.sync.aligned.m16n8k16.row.col.f32.bf16.bf16.f32 "
                 "{%0,%1,%2,%3},{%4,%5,%6,%7},{%8,%9},{%0,%1,%2,%3};"
                 : "+f"(d[0]), "+f"(d[1]), "+f"(d[2]), "+f"(d[3])
                 : "r"(a[0]), "r"(a[1]), "r"(a[2]), "r"(a[3]), "r"(b[0]), "r"(b[1]));
}

// ---------------- kernel 1: precompute + fragment packing ----------------
// B1 (k=j taps 64, col 0..127 = F^T re/im, col 128..191 = Toeplitz ks)
// B2 (k=n2 0..127 = [Sr,Si] order, col j 0..63): 2n -> Re(E), 2n+1 -> -Im(E)
__global__ __launch_bounds__(256)
void dss_precompute(const float* __restrict__ log_dt,
                    const float* __restrict__ Lambda,
                    const float* __restrict__ W) {
    int h = blockIdx.x;
    int t = threadIdx.x;

    __shared__ float2 sA[Nn][66];   // A_n^p, p=0..64
    __shared__ float2 sWk[Nn];
    __shared__ float  sks[Tt];

    if (t < Nn) {
        int n = t;
        float dt_re = expf(log_dt[h * 2 + 0]);
        float dt_im = expf(log_dt[h * 2 + 1]);
        float2 Lam = make_float2(Lambda[n * 2 + 0], Lambda[n * 2 + 1]);
        float2 z = make_float2(dt_re * Lam.x, dt_im * Lam.y);
        bool pos = (Lam.x > 0.0f);
        float2 zn = pos ? make_float2(-z.x, -z.y) : z;

        float2 ez  = cexp2(zn);
        float2 num = make_float2(ez.x - 1.0f, ez.y);
        float2 ezL = cexp2(cscale(zn, (float)Ll));
        float2 den = make_float2(ezL.x - 1.0f, ezL.y);
        float2 x   = cmul(den, Lam);
        float r2   = x.x * x.x + x.y * x.y + 1e-7f;
        float2 recip = make_float2(x.x / r2, -x.y / r2);
        float2 Wc  = make_float2(W[(h * Nn + n) * 2 + 0], W[(h * Nn + n) * 2 + 1]);
        float2 Wk  = cmul(cmul(Wc, num), recip);
        if (pos) Wk = cmul(Wk, cexp2(cscale(z, -(float)(Ll - 1))));
        sWk[n] = Wk;

        float2 A  = cexp2(z);
        float2 Ap = make_float2(1.0f, 0.0f);
        for (int p = 0; p <= 64; p++) {
            sA[n][p] = Ap;
            Ap = cmul(Ap, A);
        }
        g_G[h * Nn + n] = sA[n][64];
    }
    __syncthreads();
    if (t < Tt) {
        float acc = 0.0f;
        for (int q = 0; q < Nn; q++) acc += cmul(sWk[q], sA[q][t]).x;
        sks[t] = acc;
    }
    __syncthreads();

    // pack B1: 6144 u32 per h
    for (int i = t; i < 6144; i += 256) {
        int r    = i & 1;
        int lane = (i >> 1) & 31;
        int rest = i >> 6;
        int nt   = rest % 24;
        int ks   = rest / 24;
        int k0   = ks * 16 + (lane & 3) * 2 + r * 8;   // tap j
        int col  = nt * 8 + (lane >> 2);
        float v0, v1;
        if (col < 128) {
            float2 a0 = sA[col >> 1][63 - k0];
            float2 a1 = sA[col >> 1][63 - (k0 + 1)];
            v0 = (col & 1) ? a0.y : a0.x;
            v1 = (col & 1) ? a1.y : a1.x;
        } else {
            int jout = col - 128;
            int d0 = jout - k0;
            int d1 = jout - (k0 + 1);
            v0 = (d0 >= 0) ? sks[d0] : 0.0f;
            v1 = (d1 >= 0) ? sks[d1] : 0.0f;
        }
        uint32_t hi, lo;
        split2(v0, v1, hi, lo);
        g_B1hi[(size_t)h * 6144 + i] = hi;
        g_B1lo[(size_t)h * 6144 + i] = lo;
    }

    // pack B2: 4096 u32 per h
    for (int i = t; i < 4096; i += 256) {
        int r    = i & 1;
        int lane = (i >> 1) & 31;
        int rest = i >> 6;
        int nt   = rest & 7;
        int ks   = rest >> 3;
        int k0   = ks * 16 + (lane & 3) * 2 + r * 8;   // n2
        int j    = nt * 8 + (lane >> 2);
        float v0, v1;
        {
            int n = k0 >> 1;
            float2 e = cmul(sWk[n], sA[n][j + 1]);
            v0 = (k0 & 1) ? -e.y : e.x;
        }
        {
            int n = (k0 + 1) >> 1;
            float2 e = cmul(sWk[n], sA[n][j + 1]);
            v1 = ((k0 + 1) & 1) ? -e.y : e.x;
        }
        uint32_t hi, lo;
        split2(v0, v1, hi, lo);
        g_B2hi[(size_t)h * 4096 + i] = hi;
        g_B2lo[(size_t)h * 4096 + i] = lo;
    }
}

// ---------------- kernel 1b: split Wout into bf16 hi/lo ----------------
__global__ void splitW(const float* __restrict__ Wout) {
    int i = blockIdx.x * 256 + threadIdx.x;
    float w = Wout[i];
    __nv_bfloat16 hi = __float2bfloat16(w);
    g_Whi[i] = hi;
    g_Wlo[i] = __float2bfloat16(w - __bfloat162float(hi));
}

// ---------------- kernel 2: tensor-core chunked scan conv ----------------
// smem layout (dynamic):
//   u_hi[32][72] bf16 @0      u_lo[32][72] bf16 @4608
//   Y[32][200]  fp32  @9216   (GEMM1 out: cols 0..127 w / S_prev, 128..191 within)
//   S_hi[32][136] bf16 @34816 S_lo[32][136] bf16 @43520   (total 52224 B)
#define CONV_SMEM 52224
__global__ __launch_bounds__(256, 2)
void dss_conv(const float* __restrict__ u, const float* __restrict__ D) {
    extern __shared__ char sm[];
    __nv_bfloat16 (*u_hi)[72]  = (__nv_bfloat16(*)[72])(sm);
    __nv_bfloat16 (*u_lo)[72]  = (__nv_bfloat16(*)[72])(sm + 4608);
    float         (*Y)[200]    = (float(*)[200])(sm + 9216);
    __nv_bfloat16 (*S_hi)[136] = (__nv_bfloat16(*)[136])(sm + 34816);
    __nv_bfloat16 (*S_lo)[136] = (__nv_bfloat16(*)[136])(sm + 43520);

    int b = blockIdx.x;
    int h = blockIdx.y;
    int t = threadIdx.x;
    int lane = t & 31;
    int w = t >> 5;
    int g = lane >> 2;
    int tt = lane & 3;

    // load u (2048 fp32) -> bf16 hi/lo smem
    const float4* urow = (const float4*)(u + ((size_t)b * Hh + h) * Ll);
    #pragma unroll
    for (int k = 0; k < 2; k++) {
        int i4 = t + k * 256;
        float4 v = urow[i4];
        int c = i4 >> 4;
        int j = (i4 & 15) * 4;
        uint32_t hi, lo;
        split2(v.x, v.y, hi, lo);
        *(uint32_t*)&u_hi[c][j] = hi;
        *(uint32_t*)&u_lo[c][j] = lo;
        split2(v.z, v.w, hi, lo);
        *(uint32_t*)&u_hi[c][j + 2] = hi;
        *(uint32_t*)&u_lo[c][j + 2] = lo;
    }
    __syncthreads();

    // ---- GEMM1: M=32 (chunks) x N=192 x K=64; warp w covers cols [24w, 24w+24)
    {
        float acc[2][3][4];
        #pragma unroll
        for (int mi = 0; mi < 2; mi++)
            #pragma unroll
            for (int ni = 0; ni < 3; ni++)
                #pragma unroll
                for (int r = 0; r < 4; r++) acc[mi][ni][r] = 0.0f;

        const uint32_t* B1h = g_B1hi + (size_t)h * 6144;
        const uint32_t* B1l = g_B1lo + (size_t)h * 6144;
        int arow = lane & 15;
        int acol8 = (lane >> 4) << 3;

        #pragma unroll
        for (int ks = 0; ks < 4; ks++) {
            uint32_t ahi[2][4], alo[2][4];
            #pragma unroll
            for (int mt = 0; mt < 2; mt++) {
                ldsm_x4(ahi[mt][0], ahi[mt][1], ahi[mt][2], ahi[mt][3],
                        smem_u32(&u_hi[mt * 16 + arow][ks * 16 + acol8]));
                ldsm_x4(alo[mt][0], alo[mt][1], alo[mt][2], alo[mt][3],
                        smem_u32(&u_lo[mt * 16 + arow][ks * 16 + acol8]));
            }
            #pragma unroll
            for (int nt = 0; nt < 3; nt++) {
                int fidx = (ks * 24 + w * 3 + nt) * 64;
                uint2 bh = ((const uint2*)(B1h + fidx))[lane];
                uint2 bl = ((const uint2*)(B1l + fidx))[lane];
                uint32_t bhr[2] = {bh.x, bh.y};
                uint32_t blr[2] = {bl.x, bl.y};
                #pragma unroll
                for (int mt = 0; mt < 2; mt++) {
                    mma_bf16(acc[mt][nt], ahi[mt], bhr);
                    mma_bf16(acc[mt][nt], ahi[mt], blr);
                    mma_bf16(acc[mt][nt], alo[mt], bhr);
                }
            }
        }
        // store to Y
        #pragma unroll
        for (int mt = 0; mt < 2; mt++)
            #pragma unroll
            for (int nt = 0; nt < 3; nt++) {
                int col = w * 24 + nt * 8 + 2 * tt;
                int row = mt * 16 + g;
                Y[row][col]     = acc[mt][nt][0];
                Y[row][col + 1] = acc[mt][nt][1];
                Y[row + 8][col]     = acc[mt][nt][2];
                Y[row + 8][col + 1] = acc[mt][nt][3];
            }
    }
    __syncthreads();

    // ---- cross-chunk scan (threads 0..63), writes S_prev bf16 hi/lo
    if (t < Nn) {
        float2 G = g_G[h * Nn + t];
        float Sr = 0.0f, Si = 0.0f;
        int n2 = 2 * t;
        for (int c = 0; c < Cc; c++) {
            float wr = Y[c][n2];
            float wi = Y[c][n2 + 1];
            uint32_t hi, lo;
            split2(Sr, Si, hi, lo);
            *(uint32_t*)&S_hi[c][n2] = hi;
            *(uint32_t*)&S_lo[c][n2] = lo;
            float nr = G.x * Sr - G.y * Si + wr;
            float ni = G.x * Si + G.y * Sr + wi;
            Sr = nr; Si = ni;
        }
    }
    __syncthreads();

    // ---- GEMM2: M=32 x N=64 x K=128; warp w covers j in [8w, 8w+8)
    float acc2[2][4];
    #pragma unroll
    for (int mi = 0; mi < 2; mi++)
        #pragma unroll
        for (int r = 0; r < 4; r++) acc2[mi][r] = 0.0f;
    {
        const uint32_t* B2h = g_B2hi + (size_t)h * 4096;
        const uint32_t* B2l = g_B2lo + (size_t)h * 4096;
        int arow = lane & 15;
        int acol8 = (lane >> 4) << 3;
        #pragma unroll
        for (int ks = 0; ks < 8; ks++) {
            uint32_t ahi[2][4], alo[2][4];
            #pragma unroll
            for (int mt = 0; mt < 2; mt++) {
                ldsm_x4(ahi[mt][0], ahi[mt][1], ahi[mt][2], ahi[mt][3],
                        smem_u32(&S_hi[mt * 16 + arow][ks * 16 + acol8]));
                ldsm_x4(alo[mt][0], alo[mt][1], alo[mt][2], alo[mt][3],
                        smem_u32(&S_lo[mt * 16 + arow][ks * 16 + acol8]));
            }
            int fidx = (ks * 8 + w) * 64;
            uint2 bh = ((const uint2*)(B2h + fidx))[lane];
            uint2 bl = ((const uint2*)(B2l + fidx))[lane];
            uint32_t bhr[2] = {bh.x, bh.y};
            uint32_t blr[2] = {bl.x, bl.y};
            #pragma unroll
            for (int mt = 0; mt < 2; mt++) {
                mma_bf16(acc2[mt], ahi[mt], bhr);
                mma_bf16(acc2[mt], ahi[mt], blr);
                mma_bf16(acc2[mt], alo[mt], bhr);
            }
        }
    }

    // ---- epilogue: + within + skip, gelu, pack bf16 hi/lo
    {
        float Dh = D[h];
        size_t base = ((size_t)b * Hh + h) * Ll;
        int j0 = w * 8 + 2 * tt;
        #pragma unroll
        for (int mt = 0; mt < 2; mt++) {
            #pragma unroll
            for (int rr = 0; rr < 2; rr++) {
                int c = mt * 16 + g + rr * 8;
                float2 uh = unpack2(*(uint32_t*)&u_hi[c][j0]);
                float2 ul = unpack2(*(uint32_t*)&u_lo[c][j0]);
                float y0 = acc2[mt][rr * 2 + 0] + Y[c][128 + j0]     + Dh * (uh.x + ul.x);
                float y1 = acc2[mt][rr * 2 + 1] + Y[c][128 + j0 + 1] + Dh * (uh.y + ul.y);
                y0 = 0.5f * y0 * (1.0f + erff(y0 * 0.70710678118654752f));
                y1 = 0.5f * y1 * (1.0f + erff(y1 * 0.70710678118654752f));
                uint32_t hi, lo;
                split2(y0, y1, hi, lo);
                *(uint32_t*)&g_ghi[base + c * 64 + j0] = hi;
                *(uint32_t*)&g_glo[base + c * 64 + j0] = lo;
            }
        }
    }
}

// ---------------- kernel 3: outproj via mma.sync bf16 3-way split ----------------
__global__ __launch_bounds__(256)
void dss_outproj(const float* __restrict__ bias, float* __restrict__ out) {
    __shared__ __align__(16) __nv_bfloat16 As[2][128][40];   // [hi/lo][v][k]
    __shared__ __align__(16) __nv_bfloat16 Bs[2][32][136];   // [hi/lo][k][l]

    int b  = blockIdx.z;
    int v0 = blockIdx.y * 128;
    int l0 = blockIdx.x * 128;
    int t  = threadIdx.x;
    int lane = t & 31;
    int wrp  = t >> 5;
    int wv = wrp >> 2;
    int wl = wrp & 3;

    float acc[4][4][4];
    #pragma unroll
    for (int i = 0; i < 4; i++)
        #pragma unroll
        for (int j = 0; j < 4; j++)
            #pragma unroll
            for (int r = 0; r < 4; r++) acc[i][j][r] = 0.0f;

    const int arow = t >> 2;
    const int aseg = (t & 3) * 8;
    const int brow = t >> 4;
    const int bseg = (t & 15) * 8;

    for (int kt = 0; kt < Hh; kt += 32) {
        #pragma unroll
        for (int rep = 0; rep < 2; rep++) {
            int r128 = rep * 64 + arow;
            *(uint4*)&As[0][r128][aseg] =
                *(const uint4*)&g_Whi[(size_t)(v0 + r128) * Hh + kt + aseg];
            *(uint4*)&As[1][r128][aseg] =
                *(const uint4*)&g_Wlo[(size_t)(v0 + r128) * Hh + kt + aseg];
            int r32 = rep * 16 + brow;
            *(uint4*)&Bs[0][r32][bseg] =
                *(const uint4*)&g_ghi[((size_t)b * Hh + kt + r32) * Ll + l0 + bseg];
            *(uint4*)&Bs[1][r32][bseg] =
                *(const uint4*)&g_glo[((size_t)b * Hh + kt + r32) * Ll + l0 + bseg];
        }
        __syncthreads();

        #pragma unroll
        for (int kk = 0; kk < 2; kk++) {
            uint32_t a_hi[4][4], a_lo[4][4], b_hi[4][2], b_lo[4][2];
            int ar = (lane & 15);
            int ac = kk * 16 + ((lane >> 4) << 3);
            #pragma unroll
            for (int mi = 0; mi < 4; mi++) {
                int row = wv * 64 + mi * 16 + ar;
                ldsm_x4(a_hi[mi][0], a_hi[mi][1], a_hi[mi][2], a_hi[mi][3],
                        smem_u32(&As[0][row][ac]));
                ldsm_x4(a_lo[mi][0], a_lo[mi][1], a_lo[mi][2], a_lo[mi][3],
                        smem_u32(&As[1][row][ac]));
            }
            int brw = kk * 16 + (lane & 15);
            #pragma unroll
            for (int nj = 0; nj < 2; nj++) {
                int bc = wl * 32 + nj * 16 + ((lane >> 4) << 3);
                uint32_t r0, r1, r2, r3;
                ldsm_x4_t(r0, r1, r2, r3, smem_u32(&Bs[0][brw][bc]));
                b_hi[2 * nj][0] = r0; b_hi[2 * nj][1] = r1;
                b_hi[2 * nj + 1][0] = r2; b_hi[2 * nj + 1][1] = r3;
                ldsm_x4_t(r0, r1, r2, r3, smem_u32(&Bs[1][brw][bc]));
                b_lo[2 * nj][0] = r0; b_lo[2 * nj][1] = r1;
                b_lo[2 * nj + 1][0] = r2; b_lo[2 * nj + 1][1] = r3;
            }
            #pragma unroll
            for (int mi = 0; mi < 4; mi++)
                #pragma unroll
                for (int ni = 0; ni < 4; ni++) {
                    mma_bf16(acc[mi][ni], a_hi[mi], b_hi[ni]);
                    mma_bf16(acc[mi][ni], a_hi[mi], b_lo[ni]);
                    mma_bf16(acc[mi][ni], a_lo[mi], b_hi[ni]);
                }
        }
        __syncthreads();
    }

    int row = lane >> 2;
    int col = (lane & 3) * 2;
    #pragma unroll
    for (int mi = 0; mi < 4; mi++) {
        int v = v0 + wv * 64 + mi * 16 + row;
        float bs0 = bias[v];
        float bs1 = bias[v + 8];
        float* o0 = out + ((size_t)b * Hh + v) * Ll;
        float* o1 = out + ((size_t)b * Hh + v + 8) * Ll;
        #pragma unroll
        for (int ni = 0; ni < 4; ni++) {
            int l = l0 + wl * 32 + ni * 8 + col;
            float2 p0 = make_float2(acc[mi][ni][0] + bs0, acc[mi][ni][1] + bs0);
            float2 p1 = make_float2(acc[mi][ni][2] + bs1, acc[mi][ni][3] + bs1);
            *(float2*)&o0[l] = p0;
            *(float2*)&o1[l] = p1;
        }
    }
}

// ---------------- launch ----------------
extern "C" void kernel_launch(void* const* d_in, const int* in_sizes, int n_in,
                              void* d_out, int out_size) {
    const float* u       = (const float*)d_in[0];
    const float* log_dt  = (const float*)d_in[1];
    const float* Lambda  = (const float*)d_in[2];
    const float* W       = (const float*)d_in[3];
    const float* D       = (const float*)d_in[4];
    const float* Wout    = (const float*)d_in[5];
    const float* bias    = (const float*)d_in[6];
    float* out = (float*)d_out;

    static bool attr_set = false;
    if (!attr_set) {
        cudaFuncSetAttribute(dss_conv, cudaFuncAttributeMaxDynamicSharedMemorySize, CONV_SMEM);
        attr_set = true;
    }

    dss_precompute<<<Hh, 256>>>(log_dt, Lambda, W);
    splitW<<<Hh * Hh / 256, 256>>>(Wout);
    dss_conv<<<dim3(Bsz, Hh), 256, CONV_SMEM>>>(u, D);
    dss_outproj<<<dim3(Ll / 128, Hh / 128, Bsz), 256>>>(bias, out);
}

// round 9
// speedup vs baseline: 8.0624x; 1.2286x over previous
#include <cuda_runtime.h>
#include <cuda_bf16.h>
#include <cuda_fp16.h>
#include <cstdint>
#include <cstddef>
#include <math.h>

#define Bsz 16
#define Hh  512
#define Ll  2048
#define Nn  64
#define Tt  64
#define Cc  32

// ---------------- scratch ----------------
__device__ float2   g_G[Hh * Nn];                 // [h][n] : A^64
__device__ uint32_t g_B1h[(size_t)Hh * 6144];     // GEMM1 B frags fp16: [h][ks4][nt24][lane][2]
__device__ uint32_t g_B2h[(size_t)Hh * 4096];     // GEMM2 B frags fp16: [h][ks8][nt8][lane][2]
__device__ __half   g_ghi[(size_t)Bsz * Hh * Ll]; // gelu hi (fp16)
__device__ __half   g_glo[(size_t)Bsz * Hh * Ll]; // gelu lo (fp16)
__device__ __half   g_Wh[Hh * Hh];                // Wout fp16 [v][u]

// ---------------- helpers ----------------
__device__ __forceinline__ float2 cmul(float2 a, float2 b) {
    return make_float2(a.x * b.x - a.y * b.y, a.x * b.y + a.y * b.x);
}
__device__ __forceinline__ float2 cexp2(float2 z) {
    float e = expf(z.x);
    float s, c;
    sincosf(z.y, &s, &c);
    return make_float2(e * c, e * s);
}
__device__ __forceinline__ float2 cscale(float2 z, float s) {
    return make_float2(z.x * s, z.y * s);
}
__device__ __forceinline__ uint32_t packh(float a, float b) {
    __half2 t = __floats2half2_rn(a, b);
    return *reinterpret_cast<uint32_t*>(&t);
}
__device__ __forceinline__ float2 unpackh2(uint32_t x) {
    __half2 t = *reinterpret_cast<__half2*>(&x);
    return __half22float2(t);
}
// split pair (v0,v1) into fp16 hi and lo words
__device__ __forceinline__ void splith2(float v0, float v1, uint32_t& hi, uint32_t& lo) {
    __half2 h2 = __floats2half2_rn(v0, v1);
    hi = *reinterpret_cast<uint32_t*>(&h2);
    float r0 = v0 - __half2float(__low2half(h2));
    float r1 = v1 - __half2float(__high2half(h2));
    __half2 l2 = __floats2half2_rn(r0, r1);
    lo = *reinterpret_cast<uint32_t*>(&l2);
}
__device__ __forceinline__ uint32_t smem_u32(const void* p) {
    return (uint32_t)__cvta_generic_to_shared(p);
}
__device__ __forceinline__ void ldsm_x4(uint32_t& r0, uint32_t& r1, uint32_t& r2, uint32_t& r3, uint32_t a) {
    asm volatile("ldmatrix.sync.aligned.m8n8.x4.shared.b16 {%0,%1,%2,%3},[%4];"
                 : "=r"(r0), "=r"(r1), "=r"(r2), "=r"(r3) : "r"(a));
}
__device__ __forceinline__ void ldsm_x4_t(uint32_t& r0, uint32_t& r1, uint32_t& r2, uint32_t& r3, uint32_t a) {
    asm volatile("ldmatrix.sync.aligned.m8n8.x4.trans.shared.b16 {%0,%1,%2,%3},[%4];"
                 : "=r"(r0), "=r"(r1), "=r"(r2), "=r"(r3) : "r"(a));
}
__device__ __forceinline__ void mma_f16(float* d, const uint32_t* a, const uint32_t* b) {
    asm volatile("mma.sync.aligned.m16n8k16.row.col.f32.f16.f16.f32 "
                 "{%0,%1,%2,%3},{%4,%5,%6,%7},{%8,%9},{%0,%1,%2,%3};"
                 : "+f"(d[0]), "+f"(d[1]), "+f"(d[2]), "+f"(d[3])
                 : "r"(a[0]), "r"(a[1]), "r"(a[2]), "r"(a[3]), "r"(b[0]), "r"(b[1]));
}

// ---------------- kernel 1: precompute + fp16 fragment packing ----------------
// B1 (k=j taps 64; col 0..127 = F^T re/im, col 128..191 = Toeplitz ks)
// B2 (k=n2 0..127 in [Sr,Si] order; col j 0..63): 2n -> Re(E), 2n+1 -> -Im(E)
__global__ __launch_bounds__(256)
void dss_precompute(const float* __restrict__ log_dt,
                    const float* __restrict__ Lambda,
                    const float* __restrict__ W) {
    int h = blockIdx.x;
    int t = threadIdx.x;

    __shared__ float2 sA[Nn][66];   // A_n^p, p=0..64
    __shared__ float2 sWk[Nn];
    __shared__ float  sks[Tt];

    if (t < Nn) {
        int n = t;
        float dt_re = expf(log_dt[h * 2 + 0]);
        float dt_im = expf(log_dt[h * 2 + 1]);
        float2 Lam = make_float2(Lambda[n * 2 + 0], Lambda[n * 2 + 1]);
        float2 z = make_float2(dt_re * Lam.x, dt_im * Lam.y);
        bool pos = (Lam.x > 0.0f);
        float2 zn = pos ? make_float2(-z.x, -z.y) : z;

        float2 ez  = cexp2(zn);
        float2 num = make_float2(ez.x - 1.0f, ez.y);
        float2 ezL = cexp2(cscale(zn, (float)Ll));
        float2 den = make_float2(ezL.x - 1.0f, ezL.y);
        float2 x   = cmul(den, Lam);
        float r2   = x.x * x.x + x.y * x.y + 1e-7f;
        float2 recip = make_float2(x.x / r2, -x.y / r2);
        float2 Wc  = make_float2(W[(h * Nn + n) * 2 + 0], W[(h * Nn + n) * 2 + 1]);
        float2 Wk  = cmul(cmul(Wc, num), recip);
        if (pos) Wk = cmul(Wk, cexp2(cscale(z, -(float)(Ll - 1))));
        sWk[n] = Wk;

        float2 A  = cexp2(z);
        float2 Ap = make_float2(1.0f, 0.0f);
        for (int p = 0; p <= 64; p++) {
            sA[n][p] = Ap;
            Ap = cmul(Ap, A);
        }
        g_G[h * Nn + n] = sA[n][64];
    }
    __syncthreads();
    if (t < Tt) {
        float acc = 0.0f;
        for (int q = 0; q < Nn; q++) acc += cmul(sWk[q], sA[q][t]).x;
        sks[t] = acc;
    }
    __syncthreads();

    // pack B1: 6144 u32 per h (single fp16)
    for (int i = t; i < 6144; i += 256) {
        int r    = i & 1;
        int lane = (i >> 1) & 31;
        int rest = i >> 6;
        int nt   = rest % 24;
        int ks   = rest / 24;
        int k0   = ks * 16 + (lane & 3) * 2 + r * 8;   // tap j
        int col  = nt * 8 + (lane >> 2);
        float v0, v1;
        if (col < 128) {
            float2 a0 = sA[col >> 1][63 - k0];
            float2 a1 = sA[col >> 1][63 - (k0 + 1)];
            v0 = (col & 1) ? a0.y : a0.x;
            v1 = (col & 1) ? a1.y : a1.x;
        } else {
            int jout = col - 128;
            int d0 = jout - k0;
            int d1 = jout - (k0 + 1);
            v0 = (d0 >= 0) ? sks[d0] : 0.0f;
            v1 = (d1 >= 0) ? sks[d1] : 0.0f;
        }
        g_B1h[(size_t)h * 6144 + i] = packh(v0, v1);
    }

    // pack B2: 4096 u32 per h (single fp16)
    for (int i = t; i < 4096; i += 256) {
        int r    = i & 1;
        int lane = (i >> 1) & 31;
        int rest = i >> 6;
        int nt   = rest & 7;
        int ks   = rest >> 3;
        int k0   = ks * 16 + (lane & 3) * 2 + r * 8;   // n2
        int j    = nt * 8 + (lane >> 2);
        float v0, v1;
        {
            int n = k0 >> 1;
            float2 e = cmul(sWk[n], sA[n][j + 1]);
            v0 = (k0 & 1) ? -e.y : e.x;
        }
        {
            int n = (k0 + 1) >> 1;
            float2 e = cmul(sWk[n], sA[n][j + 1]);
            v1 = ((k0 + 1) & 1) ? -e.y : e.x;
        }
        g_B2h[(size_t)h * 4096 + i] = packh(v0, v1);
    }
}

// ---------------- kernel 1b: round Wout to fp16 ----------------
__global__ void splitW(const float* __restrict__ Wout) {
    int i = blockIdx.x * 256 + threadIdx.x;
    g_Wh[i] = __float2half_rn(Wout[i]);
}

// ---------------- kernel 2: tensor-core chunked scan conv ----------------
// smem layout (dynamic):
//   u_hi[32][72] fp16 @0      u_lo[32][72] fp16 @4608
//   Y[32][200]  fp32  @9216
//   S_hi[32][136] fp16 @34816 S_lo[32][136] fp16 @43520   (total 52224 B)
#define CONV_SMEM 52224
__global__ __launch_bounds__(256, 2)
void dss_conv(const float* __restrict__ u, const float* __restrict__ D) {
    extern __shared__ char sm[];
    __half (*u_hi)[72]  = (__half(*)[72])(sm);
    __half (*u_lo)[72]  = (__half(*)[72])(sm + 4608);
    float  (*Y)[200]    = (float(*)[200])(sm + 9216);
    __half (*S_hi)[136] = (__half(*)[136])(sm + 34816);
    __half (*S_lo)[136] = (__half(*)[136])(sm + 43520);

    int b = blockIdx.x;
    int h = blockIdx.y;
    int t = threadIdx.x;
    int lane = t & 31;
    int w = t >> 5;
    int g = lane >> 2;
    int tt = lane & 3;

    // load u (2048 fp32) -> fp16 hi/lo smem
    const float4* urow = (const float4*)(u + ((size_t)b * Hh + h) * Ll);
    #pragma unroll
    for (int k = 0; k < 2; k++) {
        int i4 = t + k * 256;
        float4 v = urow[i4];
        int c = i4 >> 4;
        int j = (i4 & 15) * 4;
        uint32_t hi, lo;
        splith2(v.x, v.y, hi, lo);
        *(uint32_t*)&u_hi[c][j] = hi;
        *(uint32_t*)&u_lo[c][j] = lo;
        splith2(v.z, v.w, hi, lo);
        *(uint32_t*)&u_hi[c][j + 2] = hi;
        *(uint32_t*)&u_lo[c][j + 2] = lo;
    }
    __syncthreads();

    // ---- GEMM1: M=32 (chunks) x N=192 x K=64; warp w covers cols [24w, 24w+24)
    {
        float acc[2][3][4];
        #pragma unroll
        for (int mi = 0; mi < 2; mi++)
            #pragma unroll
            for (int ni = 0; ni < 3; ni++)
                #pragma unroll
                for (int r = 0; r < 4; r++) acc[mi][ni][r] = 0.0f;

        const uint32_t* B1h = g_B1h + (size_t)h * 6144;
        int arow = lane & 15;
        int acol8 = (lane >> 4) << 3;

        #pragma unroll
        for (int ks = 0; ks < 4; ks++) {
            uint32_t ahi[2][4], alo[2][4];
            #pragma unroll
            for (int mt = 0; mt < 2; mt++) {
                ldsm_x4(ahi[mt][0], ahi[mt][1], ahi[mt][2], ahi[mt][3],
                        smem_u32(&u_hi[mt * 16 + arow][ks * 16 + acol8]));
                ldsm_x4(alo[mt][0], alo[mt][1], alo[mt][2], alo[mt][3],
                        smem_u32(&u_lo[mt * 16 + arow][ks * 16 + acol8]));
            }
            #pragma unroll
            for (int nt = 0; nt < 3; nt++) {
                int fidx = (ks * 24 + w * 3 + nt) * 64;
                uint2 bh = ((const uint2*)(B1h + fidx))[lane];
                uint32_t bhr[2] = {bh.x, bh.y};
                #pragma unroll
                for (int mt = 0; mt < 2; mt++) {
                    mma_f16(acc[mt][nt], ahi[mt], bhr);
                    mma_f16(acc[mt][nt], alo[mt], bhr);
                }
            }
        }
        #pragma unroll
        for (int mt = 0; mt < 2; mt++)
            #pragma unroll
            for (int nt = 0; nt < 3; nt++) {
                int col = w * 24 + nt * 8 + 2 * tt;
                int row = mt * 16 + g;
                Y[row][col]     = acc[mt][nt][0];
                Y[row][col + 1] = acc[mt][nt][1];
                Y[row + 8][col]     = acc[mt][nt][2];
                Y[row + 8][col + 1] = acc[mt][nt][3];
            }
    }
    __syncthreads();

    // ---- cross-chunk scan (threads 0..63), writes S_prev fp16 hi/lo
    if (t < Nn) {
        float2 G = g_G[h * Nn + t];
        float Sr = 0.0f, Si = 0.0f;
        int n2 = 2 * t;
        for (int c = 0; c < Cc; c++) {
            float wr = Y[c][n2];
            float wi = Y[c][n2 + 1];
            uint32_t hi, lo;
            splith2(Sr, Si, hi, lo);
            *(uint32_t*)&S_hi[c][n2] = hi;
            *(uint32_t*)&S_lo[c][n2] = lo;
            float nr = G.x * Sr - G.y * Si + wr;
            float ni = G.x * Si + G.y * Sr + wi;
            Sr = nr; Si = ni;
        }
    }
    __syncthreads();

    // ---- GEMM2: M=32 x N=64 x K=128; warp w covers j in [8w, 8w+8)
    float acc2[2][4];
    #pragma unroll
    for (int mi = 0; mi < 2; mi++)
        #pragma unroll
        for (int r = 0; r < 4; r++) acc2[mi][r] = 0.0f;
    {
        const uint32_t* B2h = g_B2h + (size_t)h * 4096;
        int arow = lane & 15;
        int acol8 = (lane >> 4) << 3;
        #pragma unroll
        for (int ks = 0; ks < 8; ks++) {
            uint32_t ahi[2][4], alo[2][4];
            #pragma unroll
            for (int mt = 0; mt < 2; mt++) {
                ldsm_x4(ahi[mt][0], ahi[mt][1], ahi[mt][2], ahi[mt][3],
                        smem_u32(&S_hi[mt * 16 + arow][ks * 16 + acol8]));
                ldsm_x4(alo[mt][0], alo[mt][1], alo[mt][2], alo[mt][3],
                        smem_u32(&S_lo[mt * 16 + arow][ks * 16 + acol8]));
            }
            int fidx = (ks * 8 + w) * 64;
            uint2 bh = ((const uint2*)(B2h + fidx))[lane];
            uint32_t bhr[2] = {bh.x, bh.y};
            #pragma unroll
            for (int mt = 0; mt < 2; mt++) {
                mma_f16(acc2[mt], ahi[mt], bhr);
                mma_f16(acc2[mt], alo[mt], bhr);
            }
        }
    }

    // ---- epilogue: + within + skip, gelu, pack fp16 hi/lo
    {
        float Dh = D[h];
        size_t base = ((size_t)b * Hh + h) * Ll;
        int j0 = w * 8 + 2 * tt;
        #pragma unroll
        for (int mt = 0; mt < 2; mt++) {
            #pragma unroll
            for (int rr = 0; rr < 2; rr++) {
                int c = mt * 16 + g + rr * 8;
                float2 uh = unpackh2(*(uint32_t*)&u_hi[c][j0]);
                float2 ul = unpackh2(*(uint32_t*)&u_lo[c][j0]);
                float y0 = acc2[mt][rr * 2 + 0] + Y[c][128 + j0]     + Dh * (uh.x + ul.x);
                float y1 = acc2[mt][rr * 2 + 1] + Y[c][128 + j0 + 1] + Dh * (uh.y + ul.y);
                y0 = 0.5f * y0 * (1.0f + erff(y0 * 0.70710678118654752f));
                y1 = 0.5f * y1 * (1.0f + erff(y1 * 0.70710678118654752f));
                uint32_t hi, lo;
                splith2(y0, y1, hi, lo);
                *(uint32_t*)&g_ghi[base + c * 64 + j0] = hi;
                *(uint32_t*)&g_glo[base + c * 64 + j0] = lo;
            }
        }
    }
}

// ---------------- kernel 3: outproj fp16 2-term ----------------
// out[b][v][l] = bias[v] + sum_u Wout[v][u] * g[b][u][l]
__global__ __launch_bounds__(256)
void dss_outproj(const float* __restrict__ bias, float* __restrict__ out) {
    __shared__ __align__(16) __half As[128][40];      // [v][k]
    __shared__ __align__(16) __half Bs[2][32][136];   // [hi/lo][k][l]

    int b  = blockIdx.z;
    int v0 = blockIdx.y * 128;
    int l0 = blockIdx.x * 128;
    int t  = threadIdx.x;
    int lane = t & 31;
    int wrp  = t >> 5;
    int wv = wrp >> 2;
    int wl = wrp & 3;

    float acc[4][4][4];
    #pragma unroll
    for (int i = 0; i < 4; i++)
        #pragma unroll
        for (int j = 0; j < 4; j++)
            #pragma unroll
            for (int r = 0; r < 4; r++) acc[i][j][r] = 0.0f;

    const int arow = t >> 2;
    const int aseg = (t & 3) * 8;
    const int brow = t >> 4;
    const int bseg = (t & 15) * 8;

    for (int kt = 0; kt < Hh; kt += 32) {
        #pragma unroll
        for (int rep = 0; rep < 2; rep++) {
            int r128 = rep * 64 + arow;
            *(uint4*)&As[r128][aseg] =
                *(const uint4*)&g_Wh[(size_t)(v0 + r128) * Hh + kt + aseg];
            int r32 = rep * 16 + brow;
            *(uint4*)&Bs[0][r32][bseg] =
                *(const uint4*)&g_ghi[((size_t)b * Hh + kt + r32) * Ll + l0 + bseg];
            *(uint4*)&Bs[1][r32][bseg] =
                *(const uint4*)&g_glo[((size_t)b * Hh + kt + r32) * Ll + l0 + bseg];
        }
        __syncthreads();

        #pragma unroll
        for (int kk = 0; kk < 2; kk++) {
            uint32_t a[4][4], b_hi[4][2], b_lo[4][2];
            int ar = (lane & 15);
            int ac = kk * 16 + ((lane >> 4) << 3);
            #pragma unroll
            for (int mi = 0; mi < 4; mi++) {
                int row = wv * 64 + mi * 16 + ar;
                ldsm_x4(a[mi][0], a[mi][1], a[mi][2], a[mi][3],
                        smem_u32(&As[row][ac]));
            }
            int brw = kk * 16 + (lane & 15);
            #pragma unroll
            for (int nj = 0; nj < 2; nj++) {
                int bc = wl * 32 + nj * 16 + ((lane >> 4) << 3);
                uint32_t r0, r1, r2, r3;
                ldsm_x4_t(r0, r1, r2, r3, smem_u32(&Bs[0][brw][bc]));
                b_hi[2 * nj][0] = r0; b_hi[2 * nj][1] = r1;
                b_hi[2 * nj + 1][0] = r2; b_hi[2 * nj + 1][1] = r3;
                ldsm_x4_t(r0, r1, r2, r3, smem_u32(&Bs[1][brw][bc]));
                b_lo[2 * nj][0] = r0; b_lo[2 * nj][1] = r1;
                b_lo[2 * nj + 1][0] = r2; b_lo[2 * nj + 1][1] = r3;
            }
            #pragma unroll
            for (int mi = 0; mi < 4; mi++)
                #pragma unroll
                for (int ni = 0; ni < 4; ni++) {
                    mma_f16(acc[mi][ni], a[mi], b_hi[ni]);
                    mma_f16(acc[mi][ni], a[mi], b_lo[ni]);
                }
        }
        __syncthreads();
    }

    int row = lane >> 2;
    int col = (lane & 3) * 2;
    #pragma unroll
    for (int mi = 0; mi < 4; mi++) {
        int v = v0 + wv * 64 + mi * 16 + row;
        float bs0 = bias[v];
        float bs1 = bias[v + 8];
        float* o0 = out + ((size_t)b * Hh + v) * Ll;
        float* o1 = out + ((size_t)b * Hh + v + 8) * Ll;
        #pragma unroll
        for (int ni = 0; ni < 4; ni++) {
            int l = l0 + wl * 32 + ni * 8 + col;
            float2 p0 = make_float2(acc[mi][ni][0] + bs0, acc[mi][ni][1] + bs0);
            float2 p1 = make_float2(acc[mi][ni][2] + bs1, acc[mi][ni][3] + bs1);
            *(float2*)&o0[l] = p0;
            *(float2*)&o1[l] = p1;
        }
    }
}

// ---------------- launch ----------------
extern "C" void kernel_launch(void* const* d_in, const int* in_sizes, int n_in,
                              void* d_out, int out_size) {
    const float* u       = (const float*)d_in[0];
    const float* log_dt  = (const float*)d_in[1];
    const float* Lambda  = (const float*)d_in[2];
    const float* W       = (const float*)d_in[3];
    const float* D       = (const float*)d_in[4];
    const float* Wout    = (const float*)d_in[5];
    const float* bias    = (const float*)d_in[6];
    float* out = (float*)d_out;

    static bool attr_set = false;
    if (!attr_set) {
        cudaFuncSetAttribute(dss_conv, cudaFuncAttributeMaxDynamicSharedMemorySize, CONV_SMEM);
        attr_set = true;
    }

    dss_precompute<<<Hh, 256>>>(log_dt, Lambda, W);
    splitW<<<Hh * Hh / 256, 256>>>(Wout);
    dss_conv<<<dim3(Bsz, Hh), 256, CONV_SMEM>>>(u, D);
    dss_outproj<<<dim3(Ll / 128, Hh / 128, Bsz), 256>>>(bias, out);
}

// round 10
// speedup vs baseline: 10.1627x; 1.2605x over previous
#include <cuda_runtime.h>
#include <cuda_bf16.h>
#include <cuda_fp16.h>
#include <cstdint>
#include <cstddef>
#include <math.h>

#define Bsz 16
#define Hh  512
#define Ll  2048
#define Nn  64
#define Tt  64
#define Cc  32

// ---------------- scratch ----------------
__device__ float2   g_G[Hh * Nn];                 // [h][n] : A^64
__device__ uint32_t g_B1h[(size_t)Hh * 6144];     // GEMM1 B frags fp16
__device__ uint32_t g_B2h[(size_t)Hh * 4096];     // GEMM2 B frags fp16
__device__ __half   g_gh[(size_t)Bsz * Hh * Ll];  // gelu (fp16, single)
__device__ __half   g_Wh[Hh * Hh];                // Wout fp16 [v][u]

// ---------------- helpers ----------------
__device__ __forceinline__ float2 cmul(float2 a, float2 b) {
    return make_float2(a.x * b.x - a.y * b.y, a.x * b.y + a.y * b.x);
}
__device__ __forceinline__ float2 cexp2(float2 z) {
    float e = expf(z.x);
    float s, c;
    sincosf(z.y, &s, &c);
    return make_float2(e * c, e * s);
}
__device__ __forceinline__ float2 cscale(float2 z, float s) {
    return make_float2(z.x * s, z.y * s);
}
__device__ __forceinline__ uint32_t packh(float a, float b) {
    __half2 t = __floats2half2_rn(a, b);
    return *reinterpret_cast<uint32_t*>(&t);
}
__device__ __forceinline__ float2 unpackh2(uint32_t x) {
    __half2 t = *reinterpret_cast<__half2*>(&x);
    return __half22float2(t);
}
__device__ __forceinline__ void splith2(float v0, float v1, uint32_t& hi, uint32_t& lo) {
    __half2 h2 = __floats2half2_rn(v0, v1);
    hi = *reinterpret_cast<uint32_t*>(&h2);
    float r0 = v0 - __half2float(__low2half(h2));
    float r1 = v1 - __half2float(__high2half(h2));
    __half2 l2 = __floats2half2_rn(r0, r1);
    lo = *reinterpret_cast<uint32_t*>(&l2);
}
__device__ __forceinline__ uint32_t smem_u32(const void* p) {
    return (uint32_t)__cvta_generic_to_shared(p);
}
__device__ __forceinline__ void cpasync16(uint32_t dst, const void* src) {
    asm volatile("cp.async.ca.shared.global [%0],[%1],16;" :: "r"(dst), "l"(src));
}
__device__ __forceinline__ void cp_commit() {
    asm volatile("cp.async.commit_group;");
}
template<int N>
__device__ __forceinline__ void cp_wait() {
    asm volatile("cp.async.wait_group %0;" :: "n"(N));
}
__device__ __forceinline__ void ldsm_x4(uint32_t& r0, uint32_t& r1, uint32_t& r2, uint32_t& r3, uint32_t a) {
    asm volatile("ldmatrix.sync.aligned.m8n8.x4.shared.b16 {%0,%1,%2,%3},[%4];"
                 : "=r"(r0), "=r"(r1), "=r"(r2), "=r"(r3) : "r"(a));
}
__device__ __forceinline__ void ldsm_x4_t(uint32_t& r0, uint32_t& r1, uint32_t& r2, uint32_t& r3, uint32_t a) {
    asm volatile("ldmatrix.sync.aligned.m8n8.x4.trans.shared.b16 {%0,%1,%2,%3},[%4];"
                 : "=r"(r0), "=r"(r1), "=r"(r2), "=r"(r3) : "r"(a));
}
__device__ __forceinline__ void mma_f16(float* d, const uint32_t* a, const uint32_t* b) {
    asm volatile("mma.sync.aligned.m16n8k16.row.col.f32.f16.f16.f32 "
                 "{%0,%1,%2,%3},{%4,%5,%6,%7},{%8,%9},{%0,%1,%2,%3};"
                 : "+f"(d[0]), "+f"(d[1]), "+f"(d[2]), "+f"(d[3])
                 : "r"(a[0]), "r"(a[1]), "r"(a[2]), "r"(a[3]), "r"(b[0]), "r"(b[1]));
}

// ---------------- kernel 1: precompute + fp16 fragment packing ----------------
__global__ __launch_bounds__(256)
void dss_precompute(const float* __restrict__ log_dt,
                    const float* __restrict__ Lambda,
                    const float* __restrict__ W) {
    int h = blockIdx.x;
    int t = threadIdx.x;

    __shared__ float2 sA[Nn][66];
    __shared__ float2 sWk[Nn];
    __shared__ float  sks[Tt];

    if (t < Nn) {
        int n = t;
        float dt_re = expf(log_dt[h * 2 + 0]);
        float dt_im = expf(log_dt[h * 2 + 1]);
        float2 Lam = make_float2(Lambda[n * 2 + 0], Lambda[n * 2 + 1]);
        float2 z = make_float2(dt_re * Lam.x, dt_im * Lam.y);
        bool pos = (Lam.x > 0.0f);
        float2 zn = pos ? make_float2(-z.x, -z.y) : z;

        float2 ez  = cexp2(zn);
        float2 num = make_float2(ez.x - 1.0f, ez.y);
        float2 ezL = cexp2(cscale(zn, (float)Ll));
        float2 den = make_float2(ezL.x - 1.0f, ezL.y);
        float2 x   = cmul(den, Lam);
        float r2   = x.x * x.x + x.y * x.y + 1e-7f;
        float2 recip = make_float2(x.x / r2, -x.y / r2);
        float2 Wc  = make_float2(W[(h * Nn + n) * 2 + 0], W[(h * Nn + n) * 2 + 1]);
        float2 Wk  = cmul(cmul(Wc, num), recip);
        if (pos) Wk = cmul(Wk, cexp2(cscale(z, -(float)(Ll - 1))));
        sWk[n] = Wk;

        float2 A  = cexp2(z);
        float2 Ap = make_float2(1.0f, 0.0f);
        for (int p = 0; p <= 64; p++) {
            sA[n][p] = Ap;
            Ap = cmul(Ap, A);
        }
        g_G[h * Nn + n] = sA[n][64];
    }
    __syncthreads();
    if (t < Tt) {
        float acc = 0.0f;
        for (int q = 0; q < Nn; q++) acc += cmul(sWk[q], sA[q][t]).x;
        sks[t] = acc;
    }
    __syncthreads();

    for (int i = t; i < 6144; i += 256) {
        int r    = i & 1;
        int lane = (i >> 1) & 31;
        int rest = i >> 6;
        int nt   = rest % 24;
        int ks   = rest / 24;
        int k0   = ks * 16 + (lane & 3) * 2 + r * 8;
        int col  = nt * 8 + (lane >> 2);
        float v0, v1;
        if (col < 128) {
            float2 a0 = sA[col >> 1][63 - k0];
            float2 a1 = sA[col >> 1][63 - (k0 + 1)];
            v0 = (col & 1) ? a0.y : a0.x;
            v1 = (col & 1) ? a1.y : a1.x;
        } else {
            int jout = col - 128;
            int d0 = jout - k0;
            int d1 = jout - (k0 + 1);
            v0 = (d0 >= 0) ? sks[d0] : 0.0f;
            v1 = (d1 >= 0) ? sks[d1] : 0.0f;
        }
        g_B1h[(size_t)h * 6144 + i] = packh(v0, v1);
    }

    for (int i = t; i < 4096; i += 256) {
        int r    = i & 1;
        int lane = (i >> 1) & 31;
        int rest = i >> 6;
        int nt   = rest & 7;
        int ks   = rest >> 3;
        int k0   = ks * 16 + (lane & 3) * 2 + r * 8;
        int j    = nt * 8 + (lane >> 2);
        float v0, v1;
        {
            int n = k0 >> 1;
            float2 e = cmul(sWk[n], sA[n][j + 1]);
            v0 = (k0 & 1) ? -e.y : e.x;
        }
        {
            int n = (k0 + 1) >> 1;
            float2 e = cmul(sWk[n], sA[n][j + 1]);
            v1 = ((k0 + 1) & 1) ? -e.y : e.x;
        }
        g_B2h[(size_t)h * 4096 + i] = packh(v0, v1);
    }
}

// ---------------- kernel 1b: round Wout to fp16 ----------------
__global__ void splitW(const float* __restrict__ Wout) {
    int i = blockIdx.x * 256 + threadIdx.x;
    g_Wh[i] = __float2half_rn(Wout[i]);
}

// ---------------- kernel 2: tensor-core chunked scan conv ----------------
#define CONV_SMEM 52224
__global__ __launch_bounds__(256, 2)
void dss_conv(const float* __restrict__ u, const float* __restrict__ D) {
    extern __shared__ char sm[];
    __half (*u_hi)[72]  = (__half(*)[72])(sm);
    __half (*u_lo)[72]  = (__half(*)[72])(sm + 4608);
    float  (*Y)[200]    = (float(*)[200])(sm + 9216);
    __half (*S_hi)[136] = (__half(*)[136])(sm + 34816);
    __half (*S_lo)[136] = (__half(*)[136])(sm + 43520);

    int b = blockIdx.x;
    int h = blockIdx.y;
    int t = threadIdx.x;
    int lane = t & 31;
    int w = t >> 5;
    int g = lane >> 2;
    int tt = lane & 3;

    const float4* urow = (const float4*)(u + ((size_t)b * Hh + h) * Ll);
    #pragma unroll
    for (int k = 0; k < 2; k++) {
        int i4 = t + k * 256;
        float4 v = urow[i4];
        int c = i4 >> 4;
        int j = (i4 & 15) * 4;
        uint32_t hi, lo;
        splith2(v.x, v.y, hi, lo);
        *(uint32_t*)&u_hi[c][j] = hi;
        *(uint32_t*)&u_lo[c][j] = lo;
        splith2(v.z, v.w, hi, lo);
        *(uint32_t*)&u_hi[c][j + 2] = hi;
        *(uint32_t*)&u_lo[c][j + 2] = lo;
    }
    __syncthreads();

    // GEMM1: M=32 x N=192 x K=64
    {
        float acc[2][3][4];
        #pragma unroll
        for (int mi = 0; mi < 2; mi++)
            #pragma unroll
            for (int ni = 0; ni < 3; ni++)
                #pragma unroll
                for (int r = 0; r < 4; r++) acc[mi][ni][r] = 0.0f;

        const uint32_t* B1h = g_B1h + (size_t)h * 6144;
        int arow = lane & 15;
        int acol8 = (lane >> 4) << 3;

        #pragma unroll
        for (int ks = 0; ks < 4; ks++) {
            uint32_t ahi[2][4], alo[2][4];
            #pragma unroll
            for (int mt = 0; mt < 2; mt++) {
                ldsm_x4(ahi[mt][0], ahi[mt][1], ahi[mt][2], ahi[mt][3],
                        smem_u32(&u_hi[mt * 16 + arow][ks * 16 + acol8]));
                ldsm_x4(alo[mt][0], alo[mt][1], alo[mt][2], alo[mt][3],
                        smem_u32(&u_lo[mt * 16 + arow][ks * 16 + acol8]));
            }
            #pragma unroll
            for (int nt = 0; nt < 3; nt++) {
                int fidx = (ks * 24 + w * 3 + nt) * 64;
                uint2 bh = ((const uint2*)(B1h + fidx))[lane];
                uint32_t bhr[2] = {bh.x, bh.y};
                #pragma unroll
                for (int mt = 0; mt < 2; mt++) {
                    mma_f16(acc[mt][nt], ahi[mt], bhr);
                    mma_f16(acc[mt][nt], alo[mt], bhr);
                }
            }
        }
        #pragma unroll
        for (int mt = 0; mt < 2; mt++)
            #pragma unroll
            for (int nt = 0; nt < 3; nt++) {
                int col = w * 24 + nt * 8 + 2 * tt;
                int row = mt * 16 + g;
                Y[row][col]     = acc[mt][nt][0];
                Y[row][col + 1] = acc[mt][nt][1];
                Y[row + 8][col]     = acc[mt][nt][2];
                Y[row + 8][col + 1] = acc[mt][nt][3];
            }
    }
    __syncthreads();

    // cross-chunk scan
    if (t < Nn) {
        float2 G = g_G[h * Nn + t];
        float Sr = 0.0f, Si = 0.0f;
        int n2 = 2 * t;
        for (int c = 0; c < Cc; c++) {
            float wr = Y[c][n2];
            float wi = Y[c][n2 + 1];
            uint32_t hi, lo;
            splith2(Sr, Si, hi, lo);
            *(uint32_t*)&S_hi[c][n2] = hi;
            *(uint32_t*)&S_lo[c][n2] = lo;
            float nr = G.x * Sr - G.y * Si + wr;
            float ni = G.x * Si + G.y * Sr + wi;
            Sr = nr; Si = ni;
        }
    }
    __syncthreads();

    // GEMM2: M=32 x N=64 x K=128
    float acc2[2][4];
    #pragma unroll
    for (int mi = 0; mi < 2; mi++)
        #pragma unroll
        for (int r = 0; r < 4; r++) acc2[mi][r] = 0.0f;
    {
        const uint32_t* B2h = g_B2h + (size_t)h * 4096;
        int arow = lane & 15;
        int acol8 = (lane >> 4) << 3;
        #pragma unroll
        for (int ks = 0; ks < 8; ks++) {
            uint32_t ahi[2][4], alo[2][4];
            #pragma unroll
            for (int mt = 0; mt < 2; mt++) {
                ldsm_x4(ahi[mt][0], ahi[mt][1], ahi[mt][2], ahi[mt][3],
                        smem_u32(&S_hi[mt * 16 + arow][ks * 16 + acol8]));
                ldsm_x4(alo[mt][0], alo[mt][1], alo[mt][2], alo[mt][3],
                        smem_u32(&S_lo[mt * 16 + arow][ks * 16 + acol8]));
            }
            int fidx = (ks * 8 + w) * 64;
            uint2 bh = ((const uint2*)(B2h + fidx))[lane];
            uint32_t bhr[2] = {bh.x, bh.y};
            #pragma unroll
            for (int mt = 0; mt < 2; mt++) {
                mma_f16(acc2[mt], ahi[mt], bhr);
                mma_f16(acc2[mt], alo[mt], bhr);
            }
        }
    }

    // epilogue: + within + skip, gelu -> single fp16
    {
        float Dh = D[h];
        size_t base = ((size_t)b * Hh + h) * Ll;
        int j0 = w * 8 + 2 * tt;
        #pragma unroll
        for (int mt = 0; mt < 2; mt++) {
            #pragma unroll
            for (int rr = 0; rr < 2; rr++) {
                int c = mt * 16 + g + rr * 8;
                float2 uh = unpackh2(*(uint32_t*)&u_hi[c][j0]);
                float2 ul = unpackh2(*(uint32_t*)&u_lo[c][j0]);
                float y0 = acc2[mt][rr * 2 + 0] + Y[c][128 + j0]     + Dh * (uh.x + ul.x);
                float y1 = acc2[mt][rr * 2 + 1] + Y[c][128 + j0 + 1] + Dh * (uh.y + ul.y);
                y0 = 0.5f * y0 * (1.0f + erff(y0 * 0.70710678118654752f));
                y1 = 0.5f * y1 * (1.0f + erff(y1 * 0.70710678118654752f));
                *(uint32_t*)&g_gh[base + c * 64 + j0] = packh(y0, y1);
            }
        }
    }
}

// ---------------- kernel 3: outproj plain fp16 GEMM, cp.async pipelined ----------------
// out[b][v][l] = bias[v] + sum_u Wh[v][u] * g[b][u][l]
__global__ __launch_bounds__(256)
void dss_outproj(const float* __restrict__ bias, float* __restrict__ out) {
    __shared__ __align__(16) __half As[2][128][40];    // [stage][v][k]
    __shared__ __align__(16) __half Bs[2][32][136];    // [stage][k][l]

    int b  = blockIdx.z;
    int v0 = blockIdx.y * 128;
    int l0 = blockIdx.x * 128;
    int t  = threadIdx.x;
    int lane = t & 31;
    int wrp  = t >> 5;
    int wv = wrp >> 2;
    int wl = wrp & 3;

    float acc[4][4][4];
    #pragma unroll
    for (int i = 0; i < 4; i++)
        #pragma unroll
        for (int j = 0; j < 4; j++)
            #pragma unroll
            for (int r = 0; r < 4; r++) acc[i][j][r] = 0.0f;

    const int arow = t >> 2;
    const int aseg = (t & 3) * 8;
    const int brow = t >> 4;
    const int bseg = (t & 15) * 8;

    // prefetch helper: stage s (k-offset s*32) into buffer s&1
    auto prefetch = [&](int s) {
        int kt = s * 32;
        int p = s & 1;
        #pragma unroll
        for (int rep = 0; rep < 2; rep++) {
            int r128 = rep * 64 + arow;
            cpasync16(smem_u32(&As[p][r128][aseg]),
                      &g_Wh[(size_t)(v0 + r128) * Hh + kt + aseg]);
            int r32 = rep * 16 + brow;
            cpasync16(smem_u32(&Bs[p][r32][bseg]),
                      &g_gh[((size_t)b * Hh + kt + r32) * Ll + l0 + bseg]);
        }
        cp_commit();
    };

    prefetch(0);

    for (int s = 0; s < 16; s++) {
        if (s + 1 < 16) {
            prefetch(s + 1);
            cp_wait<1>();
        } else {
            cp_wait<0>();
        }
        __syncthreads();

        int p = s & 1;
        #pragma unroll
        for (int kk = 0; kk < 2; kk++) {
            uint32_t a[4][4], bb[4][2];
            int ar = (lane & 15);
            int ac = kk * 16 + ((lane >> 4) << 3);
            #pragma unroll
            for (int mi = 0; mi < 4; mi++) {
                int row = wv * 64 + mi * 16 + ar;
                ldsm_x4(a[mi][0], a[mi][1], a[mi][2], a[mi][3],
                        smem_u32(&As[p][row][ac]));
            }
            int brw = kk * 16 + (lane & 15);
            #pragma unroll
            for (int nj = 0; nj < 2; nj++) {
                int bc = wl * 32 + nj * 16 + ((lane >> 4) << 3);
                uint32_t r0, r1, r2, r3;
                ldsm_x4_t(r0, r1, r2, r3, smem_u32(&Bs[p][brw][bc]));
                bb[2 * nj][0] = r0; bb[2 * nj][1] = r1;
                bb[2 * nj + 1][0] = r2; bb[2 * nj + 1][1] = r3;
            }
            #pragma unroll
            for (int mi = 0; mi < 4; mi++)
                #pragma unroll
                for (int ni = 0; ni < 4; ni++)
                    mma_f16(acc[mi][ni], a[mi], bb[ni]);
        }
        __syncthreads();
    }

    int row = lane >> 2;
    int col = (lane & 3) * 2;
    #pragma unroll
    for (int mi = 0; mi < 4; mi++) {
        int v = v0 + wv * 64 + mi * 16 + row;
        float bs0 = bias[v];
        float bs1 = bias[v + 8];
        float* o0 = out + ((size_t)b * Hh + v) * Ll;
        float* o1 = out + ((size_t)b * Hh + v + 8) * Ll;
        #pragma unroll
        for (int ni = 0; ni < 4; ni++) {
            int l = l0 + wl * 32 + ni * 8 + col;
            float2 p0 = make_float2(acc[mi][ni][0] + bs0, acc[mi][ni][1] + bs0);
            float2 p1 = make_float2(acc[mi][ni][2] + bs1, acc[mi][ni][3] + bs1);
            *(float2*)&o0[l] = p0;
            *(float2*)&o1[l] = p1;
        }
    }
}

// ---------------- launch ----------------
extern "C" void kernel_launch(void* const* d_in, const int* in_sizes, int n_in,
                              void* d_out, int out_size) {
    const float* u       = (const float*)d_in[0];
    const float* log_dt  = (const float*)d_in[1];
    const float* Lambda  = (const float*)d_in[2];
    const float* W       = (const float*)d_in[3];
    const float* D       = (const float*)d_in[4];
    const float* Wout    = (const float*)d_in[5];
    const float* bias    = (const float*)d_in[6];
    float* out = (float*)d_out;

    static bool attr_set = false;
    if (!attr_set) {
        cudaFuncSetAttribute(dss_conv, cudaFuncAttributeMaxDynamicSharedMemorySize, CONV_SMEM);
        attr_set = true;
    }

    dss_precompute<<<Hh, 256>>>(log_dt, Lambda, W);
    splitW<<<Hh * Hh / 256, 256>>>(Wout);
    dss_conv<<<dim3(Bsz, Hh), 256, CONV_SMEM>>>(u, D);
    dss_outproj<<<dim3(Ll / 128, Hh / 128, Bsz), 256>>>(bias, out);
}

// round 12
// speedup vs baseline: 11.1005x; 1.0923x over previous
#include <cuda_runtime.h>
#include <cuda_bf16.h>
#include <cuda_fp16.h>
#include <cstdint>
#include <cstddef>
#include <math.h>

#define Bsz 16
#define Hh  512
#define Ll  2048
#define Nn  64
#define Tt  64
#define Cc  32

// ---------------- scratch ----------------
__device__ float2   g_G[Hh * Nn];                 // [h][n] : A^64
__device__ uint32_t g_B1h[(size_t)Hh * 6144];     // GEMM1 B frags fp16
__device__ uint32_t g_B2h[(size_t)Hh * 4096];     // GEMM2 B frags fp16
__device__ __half   g_gh[(size_t)Bsz * Hh * Ll];  // gelu (fp16)
__device__ __half   g_Wh[Hh * Hh];                // Wout fp16 [v][u]

// ---------------- helpers ----------------
__device__ __forceinline__ float2 cmul(float2 a, float2 b) {
    return make_float2(a.x * b.x - a.y * b.y, a.x * b.y + a.y * b.x);
}
__device__ __forceinline__ float2 cexp2(float2 z) {
    float e = expf(z.x);
    float s, c;
    sincosf(z.y, &s, &c);
    return make_float2(e * c, e * s);
}
__device__ __forceinline__ float2 cscale(float2 z, float s) {
    return make_float2(z.x * s, z.y * s);
}
__device__ __forceinline__ uint32_t packh(float a, float b) {
    __half2 t = __floats2half2_rn(a, b);
    return *reinterpret_cast<uint32_t*>(&t);
}
__device__ __forceinline__ void splith2(float v0, float v1, uint32_t& hi, uint32_t& lo) {
    __half2 h2 = __floats2half2_rn(v0, v1);
    hi = *reinterpret_cast<uint32_t*>(&h2);
    float r0 = v0 - __half2float(__low2half(h2));
    float r1 = v1 - __half2float(__high2half(h2));
    __half2 l2 = __floats2half2_rn(r0, r1);
    lo = *reinterpret_cast<uint32_t*>(&l2);
}
__device__ __forceinline__ uint32_t smem_u32(const void* p) {
    return (uint32_t)__cvta_generic_to_shared(p);
}
__device__ __forceinline__ void cpasync16(uint32_t dst, const void* src) {
    asm volatile("cp.async.ca.shared.global [%0],[%1],16;" :: "r"(dst), "l"(src));
}
__device__ __forceinline__ void cp_commit() {
    asm volatile("cp.async.commit_group;");
}
template<int N>
__device__ __forceinline__ void cp_wait() {
    asm volatile("cp.async.wait_group %0;" :: "n"(N));
}
__device__ __forceinline__ void ldsm_x4(uint32_t& r0, uint32_t& r1, uint32_t& r2, uint32_t& r3, uint32_t a) {
    asm volatile("ldmatrix.sync.aligned.m8n8.x4.shared.b16 {%0,%1,%2,%3},[%4];"
                 : "=r"(r0), "=r"(r1), "=r"(r2), "=r"(r3) : "r"(a));
}
__device__ __forceinline__ void ldsm_x4_t(uint32_t& r0, uint32_t& r1, uint32_t& r2, uint32_t& r3, uint32_t a) {
    asm volatile("ldmatrix.sync.aligned.m8n8.x4.trans.shared.b16 {%0,%1,%2,%3},[%4];"
                 : "=r"(r0), "=r"(r1), "=r"(r2), "=r"(r3) : "r"(a));
}
__device__ __forceinline__ void mma_f16(float* d, const uint32_t* a, const uint32_t* b) {
    asm volatile("mma.sync.aligned.m16n8k16.row.col.f32.f16.f16.f32 "
                 "{%0,%1,%2,%3},{%4,%5,%6,%7},{%8,%9},{%0,%1,%2,%3};"
                 : "+f"(d[0]), "+f"(d[1]), "+f"(d[2]), "+f"(d[3])
                 : "r"(a[0]), "r"(a[1]), "r"(a[2]), "r"(a[3]), "r"(b[0]), "r"(b[1]));
}

// ---------------- kernel 1: precompute + fp16 fragment packing ----------------
// skip connection folded into Toeplitz: ks[0] += D[h]
__global__ __launch_bounds__(256)
void dss_precompute(const float* __restrict__ log_dt,
                    const float* __restrict__ Lambda,
                    const float* __restrict__ W,
                    const float* __restrict__ D) {
    int h = blockIdx.x;
    int t = threadIdx.x;

    __shared__ float2 sA[Nn][66];
    __shared__ float2 sWk[Nn];
    __shared__ float  sks[Tt];

    if (t < Nn) {
        int n = t;
        float dt_re = expf(log_dt[h * 2 + 0]);
        float dt_im = expf(log_dt[h * 2 + 1]);
        float2 Lam = make_float2(Lambda[n * 2 + 0], Lambda[n * 2 + 1]);
        float2 z = make_float2(dt_re * Lam.x, dt_im * Lam.y);
        bool pos = (Lam.x > 0.0f);
        float2 zn = pos ? make_float2(-z.x, -z.y) : z;

        float2 ez  = cexp2(zn);
        float2 num = make_float2(ez.x - 1.0f, ez.y);
        float2 ezL = cexp2(cscale(zn, (float)Ll));
        float2 den = make_float2(ezL.x - 1.0f, ezL.y);
        float2 x   = cmul(den, Lam);
        float r2   = x.x * x.x + x.y * x.y + 1e-7f;
        float2 recip = make_float2(x.x / r2, -x.y / r2);
        float2 Wc  = make_float2(W[(h * Nn + n) * 2 + 0], W[(h * Nn + n) * 2 + 1]);
        float2 Wk  = cmul(cmul(Wc, num), recip);
        if (pos) Wk = cmul(Wk, cexp2(cscale(z, -(float)(Ll - 1))));
        sWk[n] = Wk;

        float2 A  = cexp2(z);
        float2 Ap = make_float2(1.0f, 0.0f);
        for (int p = 0; p <= 64; p++) {
            sA[n][p] = Ap;
            Ap = cmul(Ap, A);
        }
        g_G[h * Nn + n] = sA[n][64];
    }
    __syncthreads();
    if (t < Tt) {
        float acc = (t == 0) ? D[h] : 0.0f;   // fold skip into tap 0
        for (int q = 0; q < Nn; q++) acc += cmul(sWk[q], sA[q][t]).x;
        sks[t] = acc;
    }
    __syncthreads();

    for (int i = t; i < 6144; i += 256) {
        int r    = i & 1;
        int lane = (i >> 1) & 31;
        int rest = i >> 6;
        int nt   = rest % 24;
        int ks   = rest / 24;
        int k0   = ks * 16 + (lane & 3) * 2 + r * 8;
        int col  = nt * 8 + (lane >> 2);
        float v0, v1;
        if (col < 128) {
            float2 a0 = sA[col >> 1][63 - k0];
            float2 a1 = sA[col >> 1][63 - (k0 + 1)];
            v0 = (col & 1) ? a0.y : a0.x;
            v1 = (col & 1) ? a1.y : a1.x;
        } else {
            int jout = col - 128;
            int d0 = jout - k0;
            int d1 = jout - (k0 + 1);
            v0 = (d0 >= 0) ? sks[d0] : 0.0f;
            v1 = (d1 >= 0) ? sks[d1] : 0.0f;
        }
        g_B1h[(size_t)h * 6144 + i] = packh(v0, v1);
    }

    for (int i = t; i < 4096; i += 256) {
        int r    = i & 1;
        int lane = (i >> 1) & 31;
        int rest = i >> 6;
        int nt   = rest & 7;
        int ks   = rest >> 3;
        int k0   = ks * 16 + (lane & 3) * 2 + r * 8;
        int j    = nt * 8 + (lane >> 2);
        float v0, v1;
        {
            int n = k0 >> 1;
            float2 e = cmul(sWk[n], sA[n][j + 1]);
            v0 = (k0 & 1) ? -e.y : e.x;
        }
        {
            int n = (k0 + 1) >> 1;
            float2 e = cmul(sWk[n], sA[n][j + 1]);
            v1 = ((k0 + 1) & 1) ? -e.y : e.x;
        }
        g_B2h[(size_t)h * 4096 + i] = packh(v0, v1);
    }
}

// ---------------- kernel 1b: round Wout to fp16 ----------------
__global__ void splitW(const float* __restrict__ Wout) {
    int i = blockIdx.x * 256 + threadIdx.x;
    g_Wh[i] = __float2half_rn(Wout[i]);
}

// ---------------- kernel 2: tensor-core chunked scan conv ----------------
// smem overlay (44032 B total):
//   [0,9216)      u_hi[32][72] @0, u_lo[32][72] @4608   (dead after GEMM1)
//   [0,17408)     S_hi[32][136] @0, S_lo[32][136] @8704 (born at scan)
//   [17408,34304) Yw[32][132] fp32 (w-part; dead after scan)
//   [34304,44032) Yv[32][76]  fp32 (within+skip; lives to epilogue)
#define CONV_SMEM 44032
__global__ __launch_bounds__(256, 3)
void dss_conv(const float* __restrict__ u) {
    extern __shared__ char sm[];
    __half (*u_hi)[72]  = (__half(*)[72])(sm);
    __half (*u_lo)[72]  = (__half(*)[72])(sm + 4608);
    __half (*S_hi)[136] = (__half(*)[136])(sm);
    __half (*S_lo)[136] = (__half(*)[136])(sm + 8704);
    float  (*Yw)[132]   = (float(*)[132])(sm + 17408);
    float  (*Yv)[76]    = (float(*)[76])(sm + 34304);

    int b = blockIdx.x;
    int h = blockIdx.y;
    int t = threadIdx.x;
    int lane = t & 31;
    int w = t >> 5;
    int g = lane >> 2;
    int tt = lane & 3;

    // load u (2048 fp32) -> fp16 hi/lo smem
    const float4* urow = (const float4*)(u + ((size_t)b * Hh + h) * Ll);
    #pragma unroll
    for (int k = 0; k < 2; k++) {
        int i4 = t + k * 256;
        float4 v = urow[i4];
        int c = i4 >> 4;
        int j = (i4 & 15) * 4;
        uint32_t hi, lo;
        splith2(v.x, v.y, hi, lo);
        *(uint32_t*)&u_hi[c][j] = hi;
        *(uint32_t*)&u_lo[c][j] = lo;
        splith2(v.z, v.w, hi, lo);
        *(uint32_t*)&u_hi[c][j + 2] = hi;
        *(uint32_t*)&u_lo[c][j + 2] = lo;
    }
    __syncthreads();

    // GEMM1: M=32 x N=192 x K=64; warp w covers cols [24w, 24w+24)
    {
        float acc[2][3][4];
        #pragma unroll
        for (int mi = 0; mi < 2; mi++)
            #pragma unroll
            for (int ni = 0; ni < 3; ni++)
                #pragma unroll
                for (int r = 0; r < 4; r++) acc[mi][ni][r] = 0.0f;

        const uint32_t* B1h = g_B1h + (size_t)h * 6144;
        int arow = lane & 15;
        int acol8 = (lane >> 4) << 3;

        #pragma unroll
        for (int ks = 0; ks < 4; ks++) {
            uint32_t ahi[2][4], alo[2][4];
            #pragma unroll
            for (int mt = 0; mt < 2; mt++) {
                ldsm_x4(ahi[mt][0], ahi[mt][1], ahi[mt][2], ahi[mt][3],
                        smem_u32(&u_hi[mt * 16 + arow][ks * 16 + acol8]));
                ldsm_x4(alo[mt][0], alo[mt][1], alo[mt][2], alo[mt][3],
                        smem_u32(&u_lo[mt * 16 + arow][ks * 16 + acol8]));
            }
            #pragma unroll
            for (int nt = 0; nt < 3; nt++) {
                int fidx = (ks * 24 + w * 3 + nt) * 64;
                uint2 bh = ((const uint2*)(B1h + fidx))[lane];
                uint32_t bhr[2] = {bh.x, bh.y};
                #pragma unroll
                for (int mt = 0; mt < 2; mt++) {
                    mma_f16(acc[mt][nt], ahi[mt], bhr);
                    mma_f16(acc[mt][nt], alo[mt], bhr);
                }
            }
        }
        __syncthreads();   // u reads complete before any Yw/Yv stores (S overlay later is post-scan anyway)
        #pragma unroll
        for (int mt = 0; mt < 2; mt++)
            #pragma unroll
            for (int nt = 0; nt < 3; nt++) {
                int col = w * 24 + nt * 8 + 2 * tt;
                int row = mt * 16 + g;
                if (col < 128) {
                    Yw[row][col]     = acc[mt][nt][0];
                    Yw[row][col + 1] = acc[mt][nt][1];
                    Yw[row + 8][col]     = acc[mt][nt][2];
                    Yw[row + 8][col + 1] = acc[mt][nt][3];
                } else {
                    int cv = col - 128;
                    Yv[row][cv]     = acc[mt][nt][0];
                    Yv[row][cv + 1] = acc[mt][nt][1];
                    Yv[row + 8][cv]     = acc[mt][nt][2];
                    Yv[row + 8][cv + 1] = acc[mt][nt][3];
                }
            }
    }
    __syncthreads();

    // cross-chunk scan (threads 0..63): read Yw, write S (overlays dead u)
    if (t < Nn) {
        float2 G = g_G[h * Nn + t];
        float Sr = 0.0f, Si = 0.0f;
        int n2 = 2 * t;
        for (int c = 0; c < Cc; c++) {
            float wr = Yw[c][n2];
            float wi = Yw[c][n2 + 1];
            uint32_t hi, lo;
            splith2(Sr, Si, hi, lo);
            *(uint32_t*)&S_hi[c][n2] = hi;
            *(uint32_t*)&S_lo[c][n2] = lo;
            float nr = G.x * Sr - G.y * Si + wr;
            float ni = G.x * Si + G.y * Sr + wi;
            Sr = nr; Si = ni;
        }
    }
    __syncthreads();

    // GEMM2: M=32 x N=64 x K=128; warp w covers j in [8w, 8w+8)
    float acc2[2][4];
    #pragma unroll
    for (int mi = 0; mi < 2; mi++)
        #pragma unroll
        for (int r = 0; r < 4; r++) acc2[mi][r] = 0.0f;
    {
        const uint32_t* B2h = g_B2h + (size_t)h * 4096;
        int arow = lane & 15;
        int acol8 = (lane >> 4) << 3;
        #pragma unroll
        for (int ks = 0; ks < 8; ks++) {
            uint32_t ahi[2][4], alo[2][4];
            #pragma unroll
            for (int mt = 0; mt < 2; mt++) {
                ldsm_x4(ahi[mt][0], ahi[mt][1], ahi[mt][2], ahi[mt][3],
                        smem_u32(&S_hi[mt * 16 + arow][ks * 16 + acol8]));
                ldsm_x4(alo[mt][0], alo[mt][1], alo[mt][2], alo[mt][3],
                        smem_u32(&S_lo[mt * 16 + arow][ks * 16 + acol8]));
            }
            int fidx = (ks * 8 + w) * 64;
            uint2 bh = ((const uint2*)(B2h + fidx))[lane];
            uint32_t bhr[2] = {bh.x, bh.y};
            #pragma unroll
            for (int mt = 0; mt < 2; mt++) {
                mma_f16(acc2[mt], ahi[mt], bhr);
                mma_f16(acc2[mt], alo[mt], bhr);
            }
        }
    }

    // epilogue: + (within+skip) from Yv, gelu -> fp16
    {
        size_t base = ((size_t)b * Hh + h) * Ll;
        int j0 = w * 8 + 2 * tt;
        #pragma unroll
        for (int mt = 0; mt < 2; mt++) {
            #pragma unroll
            for (int rr = 0; rr < 2; rr++) {
                int c = mt * 16 + g + rr * 8;
                float y0 = acc2[mt][rr * 2 + 0] + Yv[c][j0];
                float y1 = acc2[mt][rr * 2 + 1] + Yv[c][j0 + 1];
                y0 = 0.5f * y0 * (1.0f + erff(y0 * 0.70710678118654752f));
                y1 = 0.5f * y1 * (1.0f + erff(y1 * 0.70710678118654752f));
                *(uint32_t*)&g_gh[base + c * 64 + j0] = packh(y0, y1);
            }
        }
    }
}

// ---------------- kernel 3: outproj fp16 GEMM, cp.async pipelined ----------------
__global__ __launch_bounds__(256)
void dss_outproj(const float* __restrict__ bias, float* __restrict__ out) {
    __shared__ __align__(16) __half As[2][128][40];
    __shared__ __align__(16) __half Bs[2][32][136];

    int b  = blockIdx.z;
    int v0 = blockIdx.y * 128;
    int l0 = blockIdx.x * 128;
    int t  = threadIdx.x;
    int lane = t & 31;
    int wrp  = t >> 5;
    int wv = wrp >> 2;
    int wl = wrp & 3;

    float acc[4][4][4];
    #pragma unroll
    for (int i = 0; i < 4; i++)
        #pragma unroll
        for (int j = 0; j < 4; j++)
            #pragma unroll
            for (int r = 0; r < 4; r++) acc[i][j][r] = 0.0f;

    const int arow = t >> 2;
    const int aseg = (t & 3) * 8;
    const int brow = t >> 4;
    const int bseg = (t & 15) * 8;

    auto prefetch = [&](int s) {
        int kt = s * 32;
        int p = s & 1;
        #pragma unroll
        for (int rep = 0; rep < 2; rep++) {
            int r128 = rep * 64 + arow;
            cpasync16(smem_u32(&As[p][r128][aseg]),
                      &g_Wh[(size_t)(v0 + r128) * Hh + kt + aseg]);
            int r32 = rep * 16 + brow;
            cpasync16(smem_u32(&Bs[p][r32][bseg]),
                      &g_gh[((size_t)b * Hh + kt + r32) * Ll + l0 + bseg]);
        }
        cp_commit();
    };

    prefetch(0);

    for (int s = 0; s < 16; s++) {
        if (s + 1 < 16) {
            prefetch(s + 1);
            cp_wait<1>();
        } else {
            cp_wait<0>();
        }
        __syncthreads();

        int p = s & 1;
        #pragma unroll
        for (int kk = 0; kk < 2; kk++) {
            uint32_t a[4][4], bb[4][2];
            int ar = (lane & 15);
            int ac = kk * 16 + ((lane >> 4) << 3);
            #pragma unroll
            for (int mi = 0; mi < 4; mi++) {
                int row = wv * 64 + mi * 16 + ar;
                ldsm_x4(a[mi][0], a[mi][1], a[mi][2], a[mi][3],
                        smem_u32(&As[p][row][ac]));
            }
            int brw = kk * 16 + (lane & 15);
            #pragma unroll
            for (int nj = 0; nj < 2; nj++) {
                int bc = wl * 32 + nj * 16 + ((lane >> 4) << 3);
                uint32_t r0, r1, r2, r3;
                ldsm_x4_t(r0, r1, r2, r3, smem_u32(&Bs[p][brw][bc]));
                bb[2 * nj][0] = r0; bb[2 * nj][1] = r1;
                bb[2 * nj + 1][0] = r2; bb[2 * nj + 1][1] = r3;
            }
            #pragma unroll
            for (int mi = 0; mi < 4; mi++)
                #pragma unroll
                for (int ni = 0; ni < 4; ni++)
                    mma_f16(acc[mi][ni], a[mi], bb[ni]);
        }
        __syncthreads();
    }

    int row = lane >> 2;
    int col = (lane & 3) * 2;
    #pragma unroll
    for (int mi = 0; mi < 4; mi++) {
        int v = v0 + wv * 64 + mi * 16 + row;
        float bs0 = bias[v];
        float bs1 = bias[v + 8];
        float* o0 = out + ((size_t)b * Hh + v) * Ll;
        float* o1 = out + ((size_t)b * Hh + v + 8) * Ll;
        #pragma unroll
        for (int ni = 0; ni < 4; ni++) {
            int l = l0 + wl * 32 + ni * 8 + col;
            float2 p0 = make_float2(acc[mi][ni][0] + bs0, acc[mi][ni][1] + bs0);
            float2 p1 = make_float2(acc[mi][ni][2] + bs1, acc[mi][ni][3] + bs1);
            *(float2*)&o0[l] = p0;
            *(float2*)&o1[l] = p1;
        }
    }
}

// ---------------- launch ----------------
extern "C" void kernel_launch(void* const* d_in, const int* in_sizes, int n_in,
                              void* d_out, int out_size) {
    const float* u       = (const float*)d_in[0];
    const float* log_dt  = (const float*)d_in[1];
    const float* Lambda  = (const float*)d_in[2];
    const float* W       = (const float*)d_in[3];
    const float* D       = (const float*)d_in[4];
    const float* Wout    = (const float*)d_in[5];
    const float* bias    = (const float*)d_in[6];
    float* out = (float*)d_out;

    static bool attr_set = false;
    if (!attr_set) {
        cudaFuncSetAttribute(dss_conv, cudaFuncAttributeMaxDynamicSharedMemorySize, CONV_SMEM);
        attr_set = true;
    }

    dss_precompute<<<Hh, 256>>>(log_dt, Lambda, W, D);
    splitW<<<Hh * Hh / 256, 256>>>(Wout);
    dss_conv<<<dim3(Bsz, Hh), 256, CONV_SMEM>>>(u);
    dss_outproj<<<dim3(Ll / 128, Hh / 128, Bsz), 256>>>(bias, out);
}

// round 14
// speedup vs baseline: 13.2668x; 1.1952x over previous
#include <cuda_runtime.h>
#include <cuda_bf16.h>
#include <cuda_fp16.h>
#include <cstdint>
#include <cstddef>
#include <math.h>

#define Bsz 16
#define Hh  512
#define Ll  2048
#define Nn  64
#define Tt  64
#define Cc  32

// ---------------- scratch ----------------
__device__ float2   g_G[Hh * Nn];                 // [h][n] : A^64
__device__ uint32_t g_B1h[(size_t)Hh * 6144];     // GEMM1 B frags fp16
__device__ uint32_t g_B2h[(size_t)Hh * 4096];     // GEMM2 B frags fp16
__device__ __half   g_gh[(size_t)Bsz * Hh * Ll];  // gelu (fp16)
__device__ __half   g_Wh[Hh * Hh];                // Wout fp16 [v][u]

// ---------------- helpers ----------------
__device__ __forceinline__ float2 cmul(float2 a, float2 b) {
    return make_float2(a.x * b.x - a.y * b.y, a.x * b.y + a.y * b.x);
}
__device__ __forceinline__ float2 cexp2(float2 z) {
    float e = expf(z.x);
    float s, c;
    sincosf(z.y, &s, &c);
    return make_float2(e * c, e * s);
}
__device__ __forceinline__ float2 cscale(float2 z, float s) {
    return make_float2(z.x * s, z.y * s);
}
__device__ __forceinline__ uint32_t packh(float a, float b) {
    __half2 t = __floats2half2_rn(a, b);
    return *reinterpret_cast<uint32_t*>(&t);
}
__device__ __forceinline__ uint32_t smem_u32(const void* p) {
    return (uint32_t)__cvta_generic_to_shared(p);
}
__device__ __forceinline__ void cpasync16(uint32_t dst, const void* src) {
    asm volatile("cp.async.ca.shared.global [%0],[%1],16;" :: "r"(dst), "l"(src));
}
__device__ __forceinline__ void cp_commit() {
    asm volatile("cp.async.commit_group;");
}
template<int N>
__device__ __forceinline__ void cp_wait() {
    asm volatile("cp.async.wait_group %0;" :: "n"(N));
}
__device__ __forceinline__ void ldsm_x4(uint32_t& r0, uint32_t& r1, uint32_t& r2, uint32_t& r3, uint32_t a) {
    asm volatile("ldmatrix.sync.aligned.m8n8.x4.shared.b16 {%0,%1,%2,%3},[%4];"
                 : "=r"(r0), "=r"(r1), "=r"(r2), "=r"(r3) : "r"(a));
}
__device__ __forceinline__ void ldsm_x4_t(uint32_t& r0, uint32_t& r1, uint32_t& r2, uint32_t& r3, uint32_t a) {
    asm volatile("ldmatrix.sync.aligned.m8n8.x4.trans.shared.b16 {%0,%1,%2,%3},[%4];"
                 : "=r"(r0), "=r"(r1), "=r"(r2), "=r"(r3) : "r"(a));
}
__device__ __forceinline__ void mma_f16(float* d, const uint32_t* a, const uint32_t* b) {
    asm volatile("mma.sync.aligned.m16n8k16.row.col.f32.f16.f16.f32 "
                 "{%0,%1,%2,%3},{%4,%5,%6,%7},{%8,%9},{%0,%1,%2,%3};"
                 : "+f"(d[0]), "+f"(d[1]), "+f"(d[2]), "+f"(d[3])
                 : "r"(a[0]), "r"(a[1]), "r"(a[2]), "r"(a[3]), "r"(b[0]), "r"(b[1]));
}

// ---------------- kernel 1: precompute + fragment packing + W split ----------------
// grid (Hh, 2): y=0 packs B1 (+G), y=1 packs B2; both convert a Wout slice.
__global__ __launch_bounds__(256)
void dss_precompute(const float* __restrict__ log_dt,
                    const float* __restrict__ Lambda,
                    const float* __restrict__ W,
                    const float* __restrict__ D,
                    const float* __restrict__ Wout) {
    int h = blockIdx.x;
    int y = blockIdx.y;
    int t = threadIdx.x;

    // folded splitW: 1024 blocks x 256 threads covers 512*512
    int wi = (h * 2 + y) * 256 + t;
    g_Wh[wi] = __float2half_rn(Wout[wi]);

    __shared__ float2 sA[Nn][66];
    __shared__ float2 sWk[Nn];
    __shared__ float  sks[Tt];

    if (t < Nn) {
        int n = t;
        float dt_re = expf(log_dt[h * 2 + 0]);
        float dt_im = expf(log_dt[h * 2 + 1]);
        float2 Lam = make_float2(Lambda[n * 2 + 0], Lambda[n * 2 + 1]);
        float2 z = make_float2(dt_re * Lam.x, dt_im * Lam.y);
        bool pos = (Lam.x > 0.0f);
        float2 zn = pos ? make_float2(-z.x, -z.y) : z;

        float2 ez  = cexp2(zn);
        float2 num = make_float2(ez.x - 1.0f, ez.y);
        float2 ezL = cexp2(cscale(zn, (float)Ll));
        float2 den = make_float2(ezL.x - 1.0f, ezL.y);
        float2 x   = cmul(den, Lam);
        float r2   = x.x * x.x + x.y * x.y + 1e-7f;
        float2 recip = make_float2(x.x / r2, -x.y / r2);
        float2 Wc  = make_float2(W[(h * Nn + n) * 2 + 0], W[(h * Nn + n) * 2 + 1]);
        float2 Wk  = cmul(cmul(Wc, num), recip);
        if (pos) Wk = cmul(Wk, cexp2(cscale(z, -(float)(Ll - 1))));
        sWk[n] = Wk;

        float2 A  = cexp2(z);
        float2 Ap = make_float2(1.0f, 0.0f);
        for (int p = 0; p <= 64; p++) {
            sA[n][p] = Ap;
            Ap = cmul(Ap, A);
        }
        if (y == 0) g_G[h * Nn + n] = sA[n][64];
    }
    __syncthreads();

    if (y == 0) {
        if (t < Tt) {
            float acc = (t == 0) ? D[h] : 0.0f;   // skip folded into tap 0
            for (int q = 0; q < Nn; q++) acc += cmul(sWk[q], sA[q][t]).x;
            sks[t] = acc;
        }
        __syncthreads();
        for (int i = t; i < 6144; i += 256) {
            int r    = i & 1;
            int lane = (i >> 1) & 31;
            int rest = i >> 6;
            int nt   = rest % 24;
            int ks   = rest / 24;
            int k0   = ks * 16 + (lane & 3) * 2 + r * 8;
            int col  = nt * 8 + (lane >> 2);
            float v0, v1;
            if (col < 128) {
                float2 a0 = sA[col >> 1][63 - k0];
                float2 a1 = sA[col >> 1][63 - (k0 + 1)];
                v0 = (col & 1) ? a0.y : a0.x;
                v1 = (col & 1) ? a1.y : a1.x;
            } else {
                int jout = col - 128;
                int d0 = jout - k0;
                int d1 = jout - (k0 + 1);
                v0 = (d0 >= 0) ? sks[d0] : 0.0f;
                v1 = (d1 >= 0) ? sks[d1] : 0.0f;
            }
            g_B1h[(size_t)h * 6144 + i] = packh(v0, v1);
        }
    } else {
        for (int i = t; i < 4096; i += 256) {
            int r    = i & 1;
            int lane = (i >> 1) & 31;
            int rest = i >> 6;
            int nt   = rest & 7;
            int ks   = rest >> 3;
            int k0   = ks * 16 + (lane & 3) * 2 + r * 8;
            int j    = nt * 8 + (lane >> 2);
            float v0, v1;
            {
                int n = k0 >> 1;
                float2 e = cmul(sWk[n], sA[n][j + 1]);
                v0 = (k0 & 1) ? -e.y : e.x;
            }
            {
                int n = (k0 + 1) >> 1;
                float2 e = cmul(sWk[n], sA[n][j + 1]);
                v1 = ((k0 + 1) & 1) ? -e.y : e.x;
            }
            g_B2h[(size_t)h * 4096 + i] = packh(v0, v1);
        }
    }
}

// ---------------- kernel 2: tensor-core chunked scan conv (single fp16 u/S) ----------------
// smem overlay (35328 B):
//   [0,4608)      u_s[32][72] fp16  (dead after GEMM1)
//   [0,8704)      S_s[32][136] fp16 (born at scan)
//   [8704,25600)  Yw[32][132] fp32  (w-part; dead after scan)
//   [25600,35328) Yv[32][76]  fp32  (within+skip; lives to epilogue)
#define CONV_SMEM 35328
__global__ __launch_bounds__(256, 3)
void dss_conv(const float* __restrict__ u) {
    extern __shared__ char sm[];
    __half (*u_s)[72]  = (__half(*)[72])(sm);
    __half (*S_s)[136] = (__half(*)[136])(sm);
    float  (*Yw)[132]  = (float(*)[132])(sm + 8704);
    float  (*Yv)[76]   = (float(*)[76])(sm + 25600);

    int b = blockIdx.x;
    int h = blockIdx.y;
    int t = threadIdx.x;
    int lane = t & 31;
    int w = t >> 5;
    int g = lane >> 2;
    int tt = lane & 3;

    // load u (2048 fp32) -> single fp16 smem
    const float4* urow = (const float4*)(u + ((size_t)b * Hh + h) * Ll);
    #pragma unroll
    for (int k = 0; k < 2; k++) {
        int i4 = t + k * 256;
        float4 v = urow[i4];
        int c = i4 >> 4;
        int j = (i4 & 15) * 4;
        *(uint32_t*)&u_s[c][j]     = packh(v.x, v.y);
        *(uint32_t*)&u_s[c][j + 2] = packh(v.z, v.w);
    }
    __syncthreads();

    // GEMM1: M=32 x N=192 x K=64; warp w covers cols [24w, 24w+24)
    {
        float acc[2][3][4];
        #pragma unroll
        for (int mi = 0; mi < 2; mi++)
            #pragma unroll
            for (int ni = 0; ni < 3; ni++)
                #pragma unroll
                for (int r = 0; r < 4; r++) acc[mi][ni][r] = 0.0f;

        const uint32_t* B1h = g_B1h + (size_t)h * 6144;
        int arow = lane & 15;
        int acol8 = (lane >> 4) << 3;

        #pragma unroll
        for (int ks = 0; ks < 4; ks++) {
            uint32_t a[2][4];
            #pragma unroll
            for (int mt = 0; mt < 2; mt++)
                ldsm_x4(a[mt][0], a[mt][1], a[mt][2], a[mt][3],
                        smem_u32(&u_s[mt * 16 + arow][ks * 16 + acol8]));
            #pragma unroll
            for (int nt = 0; nt < 3; nt++) {
                int fidx = (ks * 24 + w * 3 + nt) * 64;
                uint2 bh = ((const uint2*)(B1h + fidx))[lane];
                uint32_t bhr[2] = {bh.x, bh.y};
                #pragma unroll
                for (int mt = 0; mt < 2; mt++)
                    mma_f16(acc[mt][nt], a[mt], bhr);
            }
        }
        #pragma unroll
        for (int mt = 0; mt < 2; mt++)
            #pragma unroll
            for (int nt = 0; nt < 3; nt++) {
                int col = w * 24 + nt * 8 + 2 * tt;
                int row = mt * 16 + g;
                if (col < 128) {
                    Yw[row][col]     = acc[mt][nt][0];
                    Yw[row][col + 1] = acc[mt][nt][1];
                    Yw[row + 8][col]     = acc[mt][nt][2];
                    Yw[row + 8][col + 1] = acc[mt][nt][3];
                } else {
                    int cv = col - 128;
                    Yv[row][cv]     = acc[mt][nt][0];
                    Yv[row][cv + 1] = acc[mt][nt][1];
                    Yv[row + 8][cv]     = acc[mt][nt][2];
                    Yv[row + 8][cv + 1] = acc[mt][nt][3];
                }
            }
    }
    __syncthreads();

    // cross-chunk scan (threads 0..63): read Yw, write single-fp16 S (overlays dead u)
    if (t < Nn) {
        float2 G = g_G[h * Nn + t];
        float Sr = 0.0f, Si = 0.0f;
        int n2 = 2 * t;
        for (int c = 0; c < Cc; c++) {
            float wr = Yw[c][n2];
            float wi = Yw[c][n2 + 1];
            *(uint32_t*)&S_s[c][n2] = packh(Sr, Si);
            float nr = G.x * Sr - G.y * Si + wr;
            float ni = G.x * Si + G.y * Sr + wi;
            Sr = nr; Si = ni;
        }
    }
    __syncthreads();

    // GEMM2: M=32 x N=64 x K=128; warp w covers j in [8w, 8w+8)
    float acc2[2][4];
    #pragma unroll
    for (int mi = 0; mi < 2; mi++)
        #pragma unroll
        for (int r = 0; r < 4; r++) acc2[mi][r] = 0.0f;
    {
        const uint32_t* B2h = g_B2h + (size_t)h * 4096;
        int arow = lane & 15;
        int acol8 = (lane >> 4) << 3;
        #pragma unroll
        for (int ks = 0; ks < 8; ks++) {
            uint32_t a[2][4];
            #pragma unroll
            for (int mt = 0; mt < 2; mt++)
                ldsm_x4(a[mt][0], a[mt][1], a[mt][2], a[mt][3],
                        smem_u32(&S_s[mt * 16 + arow][ks * 16 + acol8]));
            int fidx = (ks * 8 + w) * 64;
            uint2 bh = ((const uint2*)(B2h + fidx))[lane];
            uint32_t bhr[2] = {bh.x, bh.y};
            #pragma unroll
            for (int mt = 0; mt < 2; mt++)
                mma_f16(acc2[mt], a[mt], bhr);
        }
    }

    // epilogue: + (within+skip) from Yv, gelu -> fp16
    {
        size_t base = ((size_t)b * Hh + h) * Ll;
        int j0 = w * 8 + 2 * tt;
        #pragma unroll
        for (int mt = 0; mt < 2; mt++) {
            #pragma unroll
            for (int rr = 0; rr < 2; rr++) {
                int c = mt * 16 + g + rr * 8;
                float y0 = acc2[mt][rr * 2 + 0] + Yv[c][j0];
                float y1 = acc2[mt][rr * 2 + 1] + Yv[c][j0 + 1];
                y0 = 0.5f * y0 * (1.0f + erff(y0 * 0.70710678118654752f));
                y1 = 0.5f * y1 * (1.0f + erff(y1 * 0.70710678118654752f));
                *(uint32_t*)&g_gh[base + c * 64 + j0] = packh(y0, y1);
            }
        }
    }
}

// ---------------- kernel 3: outproj fp16 GEMM, 3-stage cp.async ----------------
// dynamic smem: As[3][128][40] @0 (30720 B), Bs[3][32][136] @30720 (26112 B)
#define OP_SMEM 56832
__global__ __launch_bounds__(256)
void dss_outproj(const float* __restrict__ bias, float* __restrict__ out) {
    extern __shared__ __half smo[];
    __half* Asb = smo;            // stage p at half-offset p*5120, row pitch 40
    __half* Bsb = smo + 15360;    // stage p at half-offset p*4352, row pitch 136

    int b  = blockIdx.z;
    int v0 = blockIdx.y * 128;
    int l0 = blockIdx.x * 128;
    int t  = threadIdx.x;
    int lane = t & 31;
    int wrp  = t >> 5;
    int wv = wrp >> 2;
    int wl = wrp & 3;

    float acc[4][4][4];
    #pragma unroll
    for (int i = 0; i < 4; i++)
        #pragma unroll
        for (int j = 0; j < 4; j++)
            #pragma unroll
            for (int r = 0; r < 4; r++) acc[i][j][r] = 0.0f;

    const int arow = t >> 2;
    const int aseg = (t & 3) * 8;
    const int brow = t >> 4;
    const int bseg = (t & 15) * 8;

    auto prefetch = [&](int s) {
        int kt = s * 32;
        int p = s % 3;
        #pragma unroll
        for (int rep = 0; rep < 2; rep++) {
            int r128 = rep * 64 + arow;
            cpasync16(smem_u32(Asb + p * 5120 + r128 * 40 + aseg),
                      &g_Wh[(size_t)(v0 + r128) * Hh + kt + aseg]);
            int r32 = rep * 16 + brow;
            cpasync16(smem_u32(Bsb + p * 4352 + r32 * 136 + bseg),
                      &g_gh[((size_t)b * Hh + kt + r32) * Ll + l0 + bseg]);
        }
        cp_commit();
    };

    prefetch(0);
    prefetch(1);

    for (int s = 0; s < 16; s++) {
        if (s < 14) {
            prefetch(s + 2);
            cp_wait<2>();
        } else if (s == 14) {
            cp_wait<1>();
        } else {
            cp_wait<0>();
        }
        __syncthreads();

        int p = s % 3;
        const __half* Ap = Asb + p * 5120;
        const __half* Bp = Bsb + p * 4352;
        #pragma unroll
        for (int kk = 0; kk < 2; kk++) {
            uint32_t a[4][4], bb[4][2];
            int ar = (lane & 15);
            int ac = kk * 16 + ((lane >> 4) << 3);
            #pragma unroll
            for (int mi = 0; mi < 4; mi++) {
                int row = wv * 64 + mi * 16 + ar;
                ldsm_x4(a[mi][0], a[mi][1], a[mi][2], a[mi][3],
                        smem_u32(Ap + row * 40 + ac));
            }
            int brw = kk * 16 + (lane & 15);
            #pragma unroll
            for (int nj = 0; nj < 2; nj++) {
                int bc = wl * 32 + nj * 16 + ((lane >> 4) << 3);
                uint32_t r0, r1, r2, r3;
                ldsm_x4_t(r0, r1, r2, r3, smem_u32(Bp + brw * 136 + bc));
                bb[2 * nj][0] = r0; bb[2 * nj][1] = r1;
                bb[2 * nj + 1][0] = r2; bb[2 * nj + 1][1] = r3;
            }
            #pragma unroll
            for (int mi = 0; mi < 4; mi++)
                #pragma unroll
                for (int ni = 0; ni < 4; ni++)
                    mma_f16(acc[mi][ni], a[mi], bb[ni]);
        }
        __syncthreads();
    }

    int row = lane >> 2;
    int col = (lane & 3) * 2;
    #pragma unroll
    for (int mi = 0; mi < 4; mi++) {
        int v = v0 + wv * 64 + mi * 16 + row;
        float bs0 = bias[v];
        float bs1 = bias[v + 8];
        float* o0 = out + ((size_t)b * Hh + v) * Ll;
        float* o1 = out + ((size_t)b * Hh + v + 8) * Ll;
        #pragma unroll
        for (int ni = 0; ni < 4; ni++) {
            int l = l0 + wl * 32 + ni * 8 + col;
            float2 p0 = make_float2(acc[mi][ni][0] + bs0, acc[mi][ni][1] + bs0);
            float2 p1 = make_float2(acc[mi][ni][2] + bs1, acc[mi][ni][3] + bs1);
            *(float2*)&o0[l] = p0;
            *(float2*)&o1[l] = p1;
        }
    }
}

// ---------------- launch ----------------
extern "C" void kernel_launch(void* const* d_in, const int* in_sizes, int n_in,
                              void* d_out, int out_size) {
    const float* u       = (const float*)d_in[0];
    const float* log_dt  = (const float*)d_in[1];
    const float* Lambda  = (const float*)d_in[2];
    const float* W       = (const float*)d_in[3];
    const float* D       = (const float*)d_in[4];
    const float* Wout    = (const float*)d_in[5];
    const float* bias    = (const float*)d_in[6];
    float* out = (float*)d_out;

    static bool attr_set = false;
    if (!attr_set) {
        cudaFuncSetAttribute(dss_conv, cudaFuncAttributeMaxDynamicSharedMemorySize, CONV_SMEM);
        cudaFuncSetAttribute(dss_outproj, cudaFuncAttributeMaxDynamicSharedMemorySize, OP_SMEM);
        attr_set = true;
    }

    dss_precompute<<<dim3(Hh, 2), 256>>>(log_dt, Lambda, W, D, Wout);
    dss_conv<<<dim3(Bsz, Hh), 256, CONV_SMEM>>>(u);
    dss_outproj<<<dim3(Ll / 128, Hh / 128, Bsz), 256, OP_SMEM>>>(bias, out);
}

// round 16
// speedup vs baseline: 13.2801x; 1.0010x over previous
#include <cuda_runtime.h>
#include <cuda_bf16.h>
#include <cuda_fp16.h>
#include <cstdint>
#include <cstddef>
#include <math.h>

#define Bsz 16
#define Hh  512
#define Ll  2048
#define Nn  64
#define Tt  64
#define Cc  32

// ---------------- scratch ----------------
__device__ float2   g_G[Hh * Nn];                 // [h][n] : A^64
__device__ uint32_t g_B1h[(size_t)Hh * 6144];     // GEMM1 B frags fp16
__device__ uint32_t g_B2h[(size_t)Hh * 4096];     // GEMM2 B frags fp16
__device__ __half   g_gh[(size_t)Bsz * Hh * Ll];  // gelu (fp16)
__device__ __half   g_Wh[Hh * Hh];                // Wout fp16 [v][u]

// ---------------- helpers ----------------
__device__ __forceinline__ float2 cmul(float2 a, float2 b) {
    return make_float2(a.x * b.x - a.y * b.y, a.x * b.y + a.y * b.x);
}
__device__ __forceinline__ float2 cexp2(float2 z) {
    float e = expf(z.x);
    float s, c;
    sincosf(z.y, &s, &c);
    return make_float2(e * c, e * s);
}
__device__ __forceinline__ float2 cscale(float2 z, float s) {
    return make_float2(z.x * s, z.y * s);
}
__device__ __forceinline__ uint32_t packh(float a, float b) {
    __half2 t = __floats2half2_rn(a, b);
    return *reinterpret_cast<uint32_t*>(&t);
}
__device__ __forceinline__ uint32_t smem_u32(const void* p) {
    return (uint32_t)__cvta_generic_to_shared(p);
}
__device__ __forceinline__ void cpasync16(uint32_t dst, const void* src) {
    asm volatile("cp.async.ca.shared.global [%0],[%1],16;" :: "r"(dst), "l"(src));
}
__device__ __forceinline__ void cp_commit() {
    asm volatile("cp.async.commit_group;");
}
template<int N>
__device__ __forceinline__ void cp_wait() {
    asm volatile("cp.async.wait_group %0;" :: "n"(N));
}
__device__ __forceinline__ void ldsm_x4(uint32_t& r0, uint32_t& r1, uint32_t& r2, uint32_t& r3, uint32_t a) {
    asm volatile("ldmatrix.sync.aligned.m8n8.x4.shared.b16 {%0,%1,%2,%3},[%4];"
                 : "=r"(r0), "=r"(r1), "=r"(r2), "=r"(r3) : "r"(a));
}
__device__ __forceinline__ void ldsm_x4_t(uint32_t& r0, uint32_t& r1, uint32_t& r2, uint32_t& r3, uint32_t a) {
    asm volatile("ldmatrix.sync.aligned.m8n8.x4.trans.shared.b16 {%0,%1,%2,%3},[%4];"
                 : "=r"(r0), "=r"(r1), "=r"(r2), "=r"(r3) : "r"(a));
}
__device__ __forceinline__ void mma_f16(float* d, const uint32_t* a, const uint32_t* b) {
    asm volatile("mma.sync.aligned.m16n8k16.row.col.f32.f16.f16.f32 "
                 "{%0,%1,%2,%3},{%4,%5,%6,%7},{%8,%9},{%0,%1,%2,%3};"
                 : "+f"(d[0]), "+f"(d[1]), "+f"(d[2]), "+f"(d[3])
                 : "r"(a[0]), "r"(a[1]), "r"(a[2]), "r"(a[3]), "r"(b[0]), "r"(b[1]));
}

// ---------------- kernel 1: precompute + fragment packing + W split ----------------
// grid (Hh, 2): y=0 packs B1 (+G), y=1 packs B2; both convert a Wout slice.
// power table parallelized: thread (n = t&63, q = t>>6) fills p in [16q, 16q+16(+1))
__global__ __launch_bounds__(256)
void dss_precompute(const float* __restrict__ log_dt,
                    const float* __restrict__ Lambda,
                    const float* __restrict__ W,
                    const float* __restrict__ D,
                    const float* __restrict__ Wout) {
    int h = blockIdx.x;
    int y = blockIdx.y;
    int t = threadIdx.x;
    int n = t & 63;
    int q = t >> 6;

    // folded splitW: 1024 blocks x 256 threads covers 512*512
    int wi = (h * 2 + y) * 256 + t;
    g_Wh[wi] = __float2half_rn(Wout[wi]);

    __shared__ float2 sA[Nn][66];
    __shared__ float2 sWk[Nn];
    __shared__ float  sks[Tt];
    __shared__ float  kred[Tt][4];

    // every thread computes z, Wk for its n (redundant across q; cheap)
    float dt_re = expf(log_dt[h * 2 + 0]);
    float dt_im = expf(log_dt[h * 2 + 1]);
    float2 Lam = make_float2(Lambda[n * 2 + 0], Lambda[n * 2 + 1]);
    float2 z = make_float2(dt_re * Lam.x, dt_im * Lam.y);
    bool pos = (Lam.x > 0.0f);
    float2 zn = pos ? make_float2(-z.x, -z.y) : z;

    float2 ez  = cexp2(zn);
    float2 num = make_float2(ez.x - 1.0f, ez.y);
    float2 ezL = cexp2(cscale(zn, (float)Ll));
    float2 den = make_float2(ezL.x - 1.0f, ezL.y);
    float2 x   = cmul(den, Lam);
    float r2   = x.x * x.x + x.y * x.y + 1e-7f;
    float2 recip = make_float2(x.x / r2, -x.y / r2);
    float2 Wc  = make_float2(W[(h * Nn + n) * 2 + 0], W[(h * Nn + n) * 2 + 1]);
    float2 Wk  = cmul(cmul(Wc, num), recip);
    if (pos) Wk = cmul(Wk, cexp2(cscale(z, -(float)(Ll - 1))));
    if (q == 0) sWk[n] = Wk;

    // parallel power table: 4 threads per n, 16(17) steps each
    {
        float2 A  = cexp2(z);
        float2 Ap = (q == 0) ? make_float2(1.0f, 0.0f) : cexp2(cscale(z, (float)(16 * q)));
        int pend = (q == 3) ? 65 : 16 * (q + 1);
        for (int p = 16 * q; p < pend; p++) {
            sA[n][p] = Ap;
            Ap = cmul(Ap, A);
        }
    }
    __syncthreads();
    if (y == 0 && t < Nn) g_G[h * Nn + t] = sA[t][64];

    if (y == 0) {
        // ks reduction, 4-way split over modes
        {
            int m = n;
            float acc = 0.0f;
            for (int qq = q * 16; qq < q * 16 + 16; qq++)
                acc += cmul(sWk[qq], sA[qq][m]).x;
            kred[m][q] = acc;
        }
        __syncthreads();
        if (t < Tt)
            sks[t] = kred[t][0] + kred[t][1] + kred[t][2] + kred[t][3]
                   + ((t == 0) ? D[h] : 0.0f);   // skip folded into tap 0
        __syncthreads();

        for (int i = t; i < 6144; i += 256) {
            int r    = i & 1;
            int lane = (i >> 1) & 31;
            int rest = i >> 6;
            int nt   = rest % 24;
            int ks   = rest / 24;
            int k0   = ks * 16 + (lane & 3) * 2 + r * 8;
            int col  = nt * 8 + (lane >> 2);
            float v0, v1;
            if (col < 128) {
                float2 a0 = sA[col >> 1][63 - k0];
                float2 a1 = sA[col >> 1][63 - (k0 + 1)];
                v0 = (col & 1) ? a0.y : a0.x;
                v1 = (col & 1) ? a1.y : a1.x;
            } else {
                int jout = col - 128;
                int d0 = jout - k0;
                int d1 = jout - (k0 + 1);
                v0 = (d0 >= 0) ? sks[d0] : 0.0f;
                v1 = (d1 >= 0) ? sks[d1] : 0.0f;
            }
            g_B1h[(size_t)h * 6144 + i] = packh(v0, v1);
        }
    } else {
        for (int i = t; i < 4096; i += 256) {
            int r    = i & 1;
            int lane = (i >> 1) & 31;
            int rest = i >> 6;
            int nt   = rest & 7;
            int ks   = rest >> 3;
            int k0   = ks * 16 + (lane & 3) * 2 + r * 8;
            int j    = nt * 8 + (lane >> 2);
            float v0, v1;
            {
                int nn = k0 >> 1;
                float2 e = cmul(sWk[nn], sA[nn][j + 1]);
                v0 = (k0 & 1) ? -e.y : e.x;
            }
            {
                int nn = (k0 + 1) >> 1;
                float2 e = cmul(sWk[nn], sA[nn][j + 1]);
                v1 = ((k0 + 1) & 1) ? -e.y : e.x;
            }
            g_B2h[(size_t)h * 4096 + i] = packh(v0, v1);
        }
    }
}

// ---------------- kernel 2: tensor-core chunked scan conv (single fp16 u/S) ----------------
// smem overlay (35328 B):
//   [0,4608)      u_s[32][72] fp16  (dead after GEMM1)
//   [0,8704)      S_s[32][136] fp16 (born at scan)
//   [8704,25600)  Yw[32][132] fp32  (w-part; dead after scan)
//   [25600,35328) Yv[32][76]  fp32  (within+skip; lives to epilogue)
#define CONV_SMEM 35328
__global__ __launch_bounds__(256, 3)
void dss_conv(const float* __restrict__ u) {
    extern __shared__ char sm[];
    __half (*u_s)[72]  = (__half(*)[72])(sm);
    __half (*S_s)[136] = (__half(*)[136])(sm);
    float  (*Yw)[132]  = (float(*)[132])(sm + 8704);
    float  (*Yv)[76]   = (float(*)[76])(sm + 25600);

    int b = blockIdx.x;
    int h = blockIdx.y;
    int t = threadIdx.x;
    int lane = t & 31;
    int w = t >> 5;
    int g = lane >> 2;
    int tt = lane & 3;

    // hoisted GEMM2 B-fragment loads: issue LDGs early, consume after the scan
    uint2 b2r[8];
    {
        const uint32_t* B2h = g_B2h + (size_t)h * 4096;
        #pragma unroll
        for (int ks = 0; ks < 8; ks++)
            b2r[ks] = ((const uint2*)(B2h + (ks * 8 + w) * 64))[lane];
    }

    // load u (2048 fp32) -> single fp16 smem
    const float4* urow = (const float4*)(u + ((size_t)b * Hh + h) * Ll);
    #pragma unroll
    for (int k = 0; k < 2; k++) {
        int i4 = t + k * 256;
        float4 v = urow[i4];
        int c = i4 >> 4;
        int j = (i4 & 15) * 4;
        *(uint32_t*)&u_s[c][j]     = packh(v.x, v.y);
        *(uint32_t*)&u_s[c][j + 2] = packh(v.z, v.w);
    }
    __syncthreads();

    // GEMM1: M=32 x N=192 x K=64; warp w covers cols [24w, 24w+24)
    {
        float acc[2][3][4];
        #pragma unroll
        for (int mi = 0; mi < 2; mi++)
            #pragma unroll
            for (int ni = 0; ni < 3; ni++)
                #pragma unroll
                for (int r = 0; r < 4; r++) acc[mi][ni][r] = 0.0f;

        const uint32_t* B1h = g_B1h + (size_t)h * 6144;
        int arow = lane & 15;
        int acol8 = (lane >> 4) << 3;

        #pragma unroll
        for (int ks = 0; ks < 4; ks++) {
            uint32_t a[2][4];
            #pragma unroll
            for (int mt = 0; mt < 2; mt++)
                ldsm_x4(a[mt][0], a[mt][1], a[mt][2], a[mt][3],
                        smem_u32(&u_s[mt * 16 + arow][ks * 16 + acol8]));
            #pragma unroll
            for (int nt = 0; nt < 3; nt++) {
                int fidx = (ks * 24 + w * 3 + nt) * 64;
                uint2 bh = ((const uint2*)(B1h + fidx))[lane];
                uint32_t bhr[2] = {bh.x, bh.y};
                #pragma unroll
                for (int mt = 0; mt < 2; mt++)
                    mma_f16(acc[mt][nt], a[mt], bhr);
            }
        }
        #pragma unroll
        for (int mt = 0; mt < 2; mt++)
            #pragma unroll
            for (int nt = 0; nt < 3; nt++) {
                int col = w * 24 + nt * 8 + 2 * tt;
                int row = mt * 16 + g;
                if (col < 128) {
                    Yw[row][col]     = acc[mt][nt][0];
                    Yw[row][col + 1] = acc[mt][nt][1];
                    Yw[row + 8][col]     = acc[mt][nt][2];
                    Yw[row + 8][col + 1] = acc[mt][nt][3];
                } else {
                    int cv = col - 128;
                    Yv[row][cv]     = acc[mt][nt][0];
                    Yv[row][cv + 1] = acc[mt][nt][1];
                    Yv[row + 8][cv]     = acc[mt][nt][2];
                    Yv[row + 8][cv + 1] = acc[mt][nt][3];
                }
            }
    }
    __syncthreads();

    // cross-chunk scan (threads 0..63): read Yw, write single-fp16 S (overlays dead u)
    if (t < Nn) {
        float2 G = g_G[h * Nn + t];
        float Sr = 0.0f, Si = 0.0f;
        int n2 = 2 * t;
        for (int c = 0; c < Cc; c++) {
            float wr = Yw[c][n2];
            float wi = Yw[c][n2 + 1];
            *(uint32_t*)&S_s[c][n2] = packh(Sr, Si);
            float nr = G.x * Sr - G.y * Si + wr;
            float ni = G.x * Si + G.y * Sr + wi;
            Sr = nr; Si = ni;
        }
    }
    __syncthreads();

    // GEMM2: M=32 x N=64 x K=128; warp w covers j in [8w, 8w+8)
    float acc2[2][4];
    #pragma unroll
    for (int mi = 0; mi < 2; mi++)
        #pragma unroll
        for (int r = 0; r < 4; r++) acc2[mi][r] = 0.0f;
    {
        int arow = lane & 15;
        int acol8 = (lane >> 4) << 3;
        #pragma unroll
        for (int ks = 0; ks < 8; ks++) {
            uint32_t a[2][4];
            #pragma unroll
            for (int mt = 0; mt < 2; mt++)
                ldsm_x4(a[mt][0], a[mt][1], a[mt][2], a[mt][3],
                        smem_u32(&S_s[mt * 16 + arow][ks * 16 + acol8]));
            uint32_t bhr[2] = {b2r[ks].x, b2r[ks].y};
            #pragma unroll
            for (int mt = 0; mt < 2; mt++)
                mma_f16(acc2[mt], a[mt], bhr);
        }
    }

    // epilogue: + (within+skip) from Yv, gelu -> fp16
    {
        size_t base = ((size_t)b * Hh + h) * Ll;
        int j0 = w * 8 + 2 * tt;
        #pragma unroll
        for (int mt = 0; mt < 2; mt++) {
            #pragma unroll
            for (int rr = 0; rr < 2; rr++) {
                int c = mt * 16 + g + rr * 8;
                float y0 = acc2[mt][rr * 2 + 0] + Yv[c][j0];
                float y1 = acc2[mt][rr * 2 + 1] + Yv[c][j0 + 1];
                y0 = 0.5f * y0 * (1.0f + erff(y0 * 0.70710678118654752f));
                y1 = 0.5f * y1 * (1.0f + erff(y1 * 0.70710678118654752f));
                *(uint32_t*)&g_gh[base + c * 64 + j0] = packh(y0, y1);
            }
        }
    }
}

// ---------------- kernel 3: outproj fp16 GEMM, 3-stage cp.async, 1 sync/stage ----------------
// dynamic smem: As[3][128][40] @0 (30720 B), Bs[3][32][136] @30720 (26112 B)
#define OP_SMEM 56832
__global__ __launch_bounds__(256)
void dss_outproj(const float* __restrict__ bias, float* __restrict__ out) {
    extern __shared__ __half smo[];
    __half* Asb = smo;            // stage p at half-offset p*5120, row pitch 40
    __half* Bsb = smo + 15360;    // stage p at half-offset p*4352, row pitch 136

    int b  = blockIdx.z;
    int v0 = blockIdx.y * 128;
    int l0 = blockIdx.x * 128;
    int t  = threadIdx.x;
    int lane = t & 31;
    int wrp  = t >> 5;
    int wv = wrp >> 2;
    int wl = wrp & 3;

    float acc[4][4][4];
    #pragma unroll
    for (int i = 0; i < 4; i++)
        #pragma unroll
        for (int j = 0; j < 4; j++)
            #pragma unroll
            for (int r = 0; r < 4; r++) acc[i][j][r] = 0.0f;

    const int arow = t >> 2;
    const int aseg = (t & 3) * 8;
    const int brow = t >> 4;
    const int bseg = (t & 15) * 8;

    auto prefetch = [&](int s) {
        int kt = s * 32;
        int p = s % 3;
        #pragma unroll
        for (int rep = 0; rep < 2; rep++) {
            int r128 = rep * 64 + arow;
            cpasync16(smem_u32(Asb + p * 5120 + r128 * 40 + aseg),
                      &g_Wh[(size_t)(v0 + r128) * Hh + kt + aseg]);
            int r32 = rep * 16 + brow;
            cpasync16(smem_u32(Bsb + p * 4352 + r32 * 136 + bseg),
                      &g_gh[((size_t)b * Hh + kt + r32) * Ll + l0 + bseg]);
        }
        cp_commit();
    };

    prefetch(0);
    prefetch(1);

    for (int s = 0; s < 16; s++) {
        if (s < 15) cp_wait<1>();
        else        cp_wait<0>();
        __syncthreads();               // fences prior compute AND stage-s arrival
        if (s + 2 < 16) prefetch(s + 2);  // writes stage (s+2)%3 == (s-1)%3, read finished last iter

        int p = s % 3;
        const __half* Ap = Asb + p * 5120;
        const __half* Bp = Bsb + p * 4352;
        #pragma unroll
        for (int kk = 0; kk < 2; kk++) {
            uint32_t a[4][4], bb[4][2];
            int ar = (lane & 15);
            int ac = kk * 16 + ((lane >> 4) << 3);
            #pragma unroll
            for (int mi = 0; mi < 4; mi++) {
                int row = wv * 64 + mi * 16 + ar;
                ldsm_x4(a[mi][0], a[mi][1], a[mi][2], a[mi][3],
                        smem_u32(Ap + row * 40 + ac));
            }
            int brw = kk * 16 + (lane & 15);
            #pragma unroll
            for (int nj = 0; nj < 2; nj++) {
                int bc = wl * 32 + nj * 16 + ((lane >> 4) << 3);
                uint32_t r0, r1, r2, r3;
                ldsm_x4_t(r0, r1, r2, r3, smem_u32(Bp + brw * 136 + bc));
                bb[2 * nj][0] = r0; bb[2 * nj][1] = r1;
                bb[2 * nj + 1][0] = r2; bb[2 * nj + 1][1] = r3;
            }
            #pragma unroll
            for (int mi = 0; mi < 4; mi++)
                #pragma unroll
                for (int ni = 0; ni < 4; ni++)
                    mma_f16(acc[mi][ni], a[mi], bb[ni]);
        }
    }

    int row = lane >> 2;
    int col = (lane & 3) * 2;
    #pragma unroll
    for (int mi = 0; mi < 4; mi++) {
        int v = v0 + wv * 64 + mi * 16 + row;
        float bs0 = bias[v];
        float bs1 = bias[v + 8];
        float* o0 = out + ((size_t)b * Hh + v) * Ll;
        float* o1 = out + ((size_t)b * Hh + v + 8) * Ll;
        #pragma unroll
        for (int ni = 0; ni < 4; ni++) {
            int l = l0 + wl * 32 + ni * 8 + col;
            float2 p0 = make_float2(acc[mi][ni][0] + bs0, acc[mi][ni][1] + bs0);
            float2 p1 = make_float2(acc[mi][ni][2] + bs1, acc[mi][ni][3] + bs1);
            *(float2*)&o0[l] = p0;
            *(float2*)&o1[l] = p1;
        }
    }
}

// ---------------- launch ----------------
extern "C" void kernel_launch(void* const* d_in, const int* in_sizes, int n_in,
                              void* d_out, int out_size) {
    const float* u       = (const float*)d_in[0];
    const float* log_dt  = (const float*)d_in[1];
    const float* Lambda  = (const float*)d_in[2];
    const float* W       = (const float*)d_in[3];
    const float* D       = (const float*)d_in[4];
    const float* Wout    = (const float*)d_in[5];
    const float* bias    = (const float*)d_in[6];
    float* out = (float*)d_out;

    static bool attr_set = false;
    if (!attr_set) {
        cudaFuncSetAttribute(dss_conv, cudaFuncAttributeMaxDynamicSharedMemorySize, CONV_SMEM);
        cudaFuncSetAttribute(dss_outproj, cudaFuncAttributeMaxDynamicSharedMemorySize, OP_SMEM);
        attr_set = true;
    }

    dss_precompute<<<dim3(Hh, 2), 256>>>(log_dt, Lambda, W, D, Wout);
    dss_conv<<<dim3(Bsz, Hh), 256, CONV_SMEM>>>(u);
    dss_outproj<<<dim3(Ll / 128, Hh / 128, Bsz), 256, OP_SMEM>>>(bias, out);
}